// round 2
// baseline (speedup 1.0000x reference)
#include <cuda_runtime.h>
#include <math.h>

#define H 128
#define MAX_SRC 20000
#define MAX_DST 20000
#define MAX_E   640000

// ---------------- device scratch (no runtime allocation) ----------------
__device__ float g_hidden[MAX_SRC * H];
__device__ float g_h[MAX_SRC * H];
__device__ float g_agg[MAX_DST * 4 * H];
__device__ int   g_cnt[MAX_DST];
__device__ int   g_off[MAX_DST + 1];
__device__ int   g_cursor[MAX_DST];
__device__ int   g_perm[MAX_E];

// ---------------- CSR build ----------------
__global__ void zero_cnt_kernel(int n_dst) {
    int i = blockIdx.x * blockDim.x + threadIdx.x;
    if (i < n_dst) g_cnt[i] = 0;
}

__global__ void count_kernel(const int* __restrict__ edge_dst, int E) {
    int i = blockIdx.x * blockDim.x + threadIdx.x;
    if (i < E) atomicAdd(&g_cnt[edge_dst[i]], 1);
}

// single-block exclusive scan of g_cnt -> g_off / g_cursor
__global__ void scan_kernel(int n) {
    __shared__ int s[1024];
    __shared__ int carry;
    int tid = threadIdx.x;
    if (tid == 0) carry = 0;
    __syncthreads();
    for (int base = 0; base < n; base += 1024) {
        int i = base + tid;
        int v = (i < n) ? g_cnt[i] : 0;
        s[tid] = v;
        __syncthreads();
        for (int d = 1; d < 1024; d <<= 1) {
            int t = (tid >= d) ? s[tid - d] : 0;
            __syncthreads();
            s[tid] += t;
            __syncthreads();
        }
        int incl = s[tid];
        int excl = incl - v;
        if (i < n) {
            g_off[i] = carry + excl;
            g_cursor[i] = carry + excl;
        }
        __syncthreads();
        if (tid == 1023) carry += s[1023];
        __syncthreads();
    }
    if (tid == 0) g_off[n] = carry;
}

__global__ void scatter_kernel(const int* __restrict__ edge_src,
                               const int* __restrict__ edge_dst, int E) {
    int i = blockIdx.x * blockDim.x + threadIdx.x;
    if (i < E) {
        int d = edge_dst[i];
        int p = atomicAdd(&g_cursor[d], 1);
        g_perm[p] = edge_src[i];
    }
}

// ---------------- aggregation: warp per dst, atomic-free ----------------
__global__ void agg_kernel(const float* __restrict__ dst_feat, int n_dst) {
    int warp = (blockIdx.x * blockDim.x + threadIdx.x) >> 5;
    int lane = threadIdx.x & 31;
    if (warp >= n_dst) return;
    int d = warp;
    int beg = g_off[d], end = g_off[d + 1];
    const float4* hv = (const float4*)g_h;

    float4 sum = make_float4(0.f, 0.f, 0.f, 0.f);
    float4 mx  = make_float4(-3.4e38f, -3.4e38f, -3.4e38f, -3.4e38f);

    int e = beg;
    for (; e + 1 < end; e += 2) {
        int s0 = g_perm[e];
        int s1 = g_perm[e + 1];
        float4 v0 = hv[s0 * 32 + lane];
        float4 v1 = hv[s1 * 32 + lane];
        sum.x += v0.x; sum.y += v0.y; sum.z += v0.z; sum.w += v0.w;
        mx.x = fmaxf(mx.x, v0.x); mx.y = fmaxf(mx.y, v0.y);
        mx.z = fmaxf(mx.z, v0.z); mx.w = fmaxf(mx.w, v0.w);
        sum.x += v1.x; sum.y += v1.y; sum.z += v1.z; sum.w += v1.w;
        mx.x = fmaxf(mx.x, v1.x); mx.y = fmaxf(mx.y, v1.y);
        mx.z = fmaxf(mx.z, v1.z); mx.w = fmaxf(mx.w, v1.w);
    }
    if (e < end) {
        int s0 = g_perm[e];
        float4 v0 = hv[s0 * 32 + lane];
        sum.x += v0.x; sum.y += v0.y; sum.z += v0.z; sum.w += v0.w;
        mx.x = fmaxf(mx.x, v0.x); mx.y = fmaxf(mx.y, v0.y);
        mx.z = fmaxf(mx.z, v0.z); mx.w = fmaxf(mx.w, v0.w);
    }

    int cnt = end - beg;
    if (cnt == 0) mx = make_float4(0.f, 0.f, 0.f, 0.f);
    float inv = 1.0f / (float)(cnt > 0 ? cnt : 1);
    float4 mean = make_float4(sum.x * inv, sum.y * inv, sum.z * inv, sum.w * inv);

    float4* out = (float4*)(g_agg + (size_t)d * 4 * H);
    const float4* dfv = (const float4*)dst_feat;
    out[lane]       = sum;
    out[32 + lane]  = mx;
    out[64 + lane]  = mean;
    out[96 + lane]  = dfv[d * 32 + lane];
}

// ---------------- fused GEMM (C = epi(A @ W + b) [+ res]) ----------------
// BM=128, BN=128(=H), BK=16, 256 threads, 8x8 per thread, double-buffered.
#define BM 128
#define BN 128
#define BK 16

// MODE 0: A=param(src_feat), C=g_hidden, lrelu, no residual
// MODE 1: A=g_hidden,        C=g_h,      no lrelu, residual=param(src_feat)
// MODE 2: A=g_agg,           C=param(d_out), lrelu, residual=param(dst_feat)
template <int MODE>
__global__ __launch_bounds__(256) void gemm_kernel(
    const float* __restrict__ Ap, const float* __restrict__ W,
    const float* __restrict__ bias, const float* __restrict__ res,
    float* __restrict__ Cp, int M, int K)
{
    const float* A = (MODE == 1) ? g_hidden : (MODE == 2) ? g_agg : Ap;
    float* C = (MODE == 0) ? g_hidden : (MODE == 1) ? g_h : Cp;
    constexpr bool LRELU = (MODE != 1);
    constexpr bool RESID = (MODE != 0);

    __shared__ float As[2][BK][BM];
    __shared__ float Ws[2][BK][BN];

    int tid = threadIdx.x;
    int block_row = blockIdx.x * BM;
    int tx = tid & 15, ty = tid >> 4;

    int a_row[2], a_col[2], w_k[2], w_n[2];
#pragma unroll
    for (int l = 0; l < 2; l++) {
        int flat = tid + l * 256;
        a_row[l] = flat >> 2;
        a_col[l] = (flat & 3) * 4;
        w_k[l] = flat >> 5;
        w_n[l] = (flat & 31) * 4;
    }

    float4 a_reg[2], w_reg[2];
    int ntiles = K / BK;

    auto fetch = [&](int t) {
#pragma unroll
        for (int l = 0; l < 2; l++) {
            int rg = block_row + a_row[l];
            if (rg < M)
                a_reg[l] = *(const float4*)(A + (size_t)rg * K + t * BK + a_col[l]);
            else
                a_reg[l] = make_float4(0.f, 0.f, 0.f, 0.f);
            w_reg[l] = *(const float4*)(W + (size_t)(t * BK + w_k[l]) * BN + w_n[l]);
        }
    };
    auto stage = [&](int buf) {
#pragma unroll
        for (int l = 0; l < 2; l++) {
            As[buf][a_col[l] + 0][a_row[l]] = a_reg[l].x;
            As[buf][a_col[l] + 1][a_row[l]] = a_reg[l].y;
            As[buf][a_col[l] + 2][a_row[l]] = a_reg[l].z;
            As[buf][a_col[l] + 3][a_row[l]] = a_reg[l].w;
            *(float4*)&Ws[buf][w_k[l]][w_n[l]] = w_reg[l];
        }
    };

    float acc[8][8] = {};
    fetch(0);
    stage(0);
    __syncthreads();

    for (int t = 0; t < ntiles; t++) {
        if (t + 1 < ntiles) fetch(t + 1);
        int buf = t & 1;
#pragma unroll
        for (int k = 0; k < BK; k++) {
            float4 a0 = *(const float4*)&As[buf][k][ty * 8];
            float4 a1 = *(const float4*)&As[buf][k][ty * 8 + 4];
            float4 b0 = *(const float4*)&Ws[buf][k][tx * 8];
            float4 b1 = *(const float4*)&Ws[buf][k][tx * 8 + 4];
            float av[8] = {a0.x, a0.y, a0.z, a0.w, a1.x, a1.y, a1.z, a1.w};
            float bv[8] = {b0.x, b0.y, b0.z, b0.w, b1.x, b1.y, b1.z, b1.w};
#pragma unroll
            for (int i = 0; i < 8; i++)
#pragma unroll
                for (int j = 0; j < 8; j++)
                    acc[i][j] = fmaf(av[i], bv[j], acc[i][j]);
        }
        if (t + 1 < ntiles) stage((t + 1) & 1);
        __syncthreads();
    }

    float bv[8];
#pragma unroll
    for (int j = 0; j < 8; j++) bv[j] = bias[tx * 8 + j];

#pragma unroll
    for (int i = 0; i < 8; i++) {
        int rg = block_row + ty * 8 + i;
        if (rg >= M) continue;
#pragma unroll
        for (int j = 0; j < 8; j++) {
            float v = acc[i][j] + bv[j];
            if (LRELU) v = v > 0.f ? v : 0.1f * v;
            if (RESID) v += res[(size_t)rg * H + tx * 8 + j];
            C[(size_t)rg * H + tx * 8 + j] = v;
        }
    }
}

// ---------------- launch ----------------
extern "C" void kernel_launch(void* const* d_in, const int* in_sizes, int n_in,
                              void* d_out, int out_size) {
    const float* src_feat = (const float*)d_in[0];
    const float* dst_feat = (const float*)d_in[1];
    const int*   edge_src = (const int*)d_in[2];
    const int*   edge_dst = (const int*)d_in[3];
    const float* W1 = (const float*)d_in[4];
    const float* b1 = (const float*)d_in[5];
    const float* W2 = (const float*)d_in[6];
    const float* b2 = (const float*)d_in[7];
    const float* Wr = (const float*)d_in[8];
    const float* br = (const float*)d_in[9];
    float* out = (float*)d_out;

    int n_src = in_sizes[0] / H;
    int n_dst = in_sizes[1] / H;
    int E     = in_sizes[2];

    int gm_src = (n_src + BM - 1) / BM;
    int gm_dst = (n_dst + BM - 1) / BM;

    // CSR build
    zero_cnt_kernel<<<(n_dst + 255) / 256, 256>>>(n_dst);
    count_kernel<<<(E + 255) / 256, 256>>>(edge_dst, E);
    scan_kernel<<<1, 1024>>>(n_dst);
    scatter_kernel<<<(E + 255) / 256, 256>>>(edge_src, edge_dst, E);

    // src MLP: hidden = lrelu(src@W1+b1); h = src + hidden@W2 + b2
    gemm_kernel<0><<<gm_src, 256>>>(src_feat, W1, b1, nullptr, nullptr, n_src, H);
    gemm_kernel<1><<<gm_src, 256>>>(nullptr, W2, b2, src_feat, nullptr, n_src, H);

    // per-dst sum/max/mean + concat(dst_feat)
    agg_kernel<<<(n_dst * 32 + 255) / 256, 256>>>(dst_feat, n_dst);

    // readout: out = dst_feat + lrelu(agg @ Wr + br)
    gemm_kernel<2><<<gm_dst, 256>>>(nullptr, Wr, br, dst_feat, out, n_dst, 4 * H);
}

// round 3
// speedup vs baseline: 1.1376x; 1.1376x over previous
#include <cuda_runtime.h>
#include <math.h>

#define H 128
#define MAX_SRC 20000
#define MAX_DST 20000
#define MAX_E   640000

// ---------------- device scratch (no runtime allocation) ----------------
__device__ float g_hidden[MAX_SRC * H];
__device__ float g_h[MAX_SRC * H];
__device__ float g_agg[MAX_DST * 4 * H];
__device__ int   g_cnt[MAX_DST];
__device__ int   g_off[MAX_DST + 1];
__device__ int   g_cursor[MAX_DST];
__device__ int   g_perm[MAX_E];
__device__ int   g_bsum[32];
__device__ int   g_bpre[32];

// ---------------- CSR build ----------------
__global__ void zero_cnt_kernel(int n_dst) {
    int i = blockIdx.x * blockDim.x + threadIdx.x;
    if (i < n_dst) g_cnt[i] = 0;
}

// 4 edges per thread for MLP
__global__ void count_kernel(const int* __restrict__ edge_dst, int E) {
    int i = (blockIdx.x * blockDim.x + threadIdx.x) * 4;
    int d0 = (i + 0 < E) ? edge_dst[i + 0] : -1;
    int d1 = (i + 1 < E) ? edge_dst[i + 1] : -1;
    int d2 = (i + 2 < E) ? edge_dst[i + 2] : -1;
    int d3 = (i + 3 < E) ? edge_dst[i + 3] : -1;
    if (d0 >= 0) atomicAdd(&g_cnt[d0], 1);
    if (d1 >= 0) atomicAdd(&g_cnt[d1], 1);
    if (d2 >= 0) atomicAdd(&g_cnt[d2], 1);
    if (d3 >= 0) atomicAdd(&g_cnt[d3], 1);
}

// multi-block scan: phase 1 — block-local exclusive scan + block totals
__global__ void scan_block_kernel(int n) {
    __shared__ int s[1024];
    int tid = threadIdx.x;
    int i = blockIdx.x * 1024 + tid;
    int v = (i < n) ? g_cnt[i] : 0;
    s[tid] = v;
    __syncthreads();
    for (int d = 1; d < 1024; d <<= 1) {
        int t = (tid >= d) ? s[tid - d] : 0;
        __syncthreads();
        s[tid] += t;
        __syncthreads();
    }
    if (i < n) g_off[i] = s[tid] - v;  // block-local exclusive
    if (tid == 1023) g_bsum[blockIdx.x] = s[1023];
}

// phase 2 — warp-scan the (<=32) block totals
__global__ void scan_partials_kernel(int nb, int n) {
    int tid = threadIdx.x;  // 32 threads
    int v0 = (tid < nb) ? g_bsum[tid] : 0;
    int v = v0;
    for (int d = 1; d < 32; d <<= 1) {
        int t = __shfl_up_sync(0xffffffffu, v, d);
        if (tid >= d) v += t;
    }
    if (tid < nb) g_bpre[tid] = v - v0;  // exclusive
    if (tid == 31) g_off[n] = v;         // grand total
}

// phase 3 — add block prefixes, init cursors
__global__ void scan_add_kernel(int n) {
    int i = blockIdx.x * 1024 + threadIdx.x;
    if (i < n) {
        int o = g_off[i] + g_bpre[blockIdx.x];
        g_off[i] = o;
        g_cursor[i] = o;
    }
}

// 4 edges per thread for MLP
__global__ void scatter_kernel(const int* __restrict__ edge_src,
                               const int* __restrict__ edge_dst, int E) {
    int i = (blockIdx.x * blockDim.x + threadIdx.x) * 4;
#pragma unroll
    for (int j = 0; j < 4; j++) {
        if (i + j < E) {
            int d = edge_dst[i + j];
            int s = edge_src[i + j];
            int p = atomicAdd(&g_cursor[d], 1);
            g_perm[p] = s;
        }
    }
}

// ---------------- aggregation: warp per dst, atomic-free, 4-way ILP ----------------
__global__ void agg_kernel(const float* __restrict__ dst_feat, int n_dst) {
    int warp = (blockIdx.x * blockDim.x + threadIdx.x) >> 5;
    int lane = threadIdx.x & 31;
    if (warp >= n_dst) return;
    int d = warp;
    int beg = g_off[d], end = g_off[d + 1];
    const float4* __restrict__ hv = (const float4*)g_h;

    float4 sum = make_float4(0.f, 0.f, 0.f, 0.f);
    float4 mx  = make_float4(-3.4e38f, -3.4e38f, -3.4e38f, -3.4e38f);

    int e = beg;
    for (; e + 3 < end; e += 4) {
        int s0 = g_perm[e];
        int s1 = g_perm[e + 1];
        int s2 = g_perm[e + 2];
        int s3 = g_perm[e + 3];
        float4 v0 = hv[s0 * 32 + lane];
        float4 v1 = hv[s1 * 32 + lane];
        float4 v2 = hv[s2 * 32 + lane];
        float4 v3 = hv[s3 * 32 + lane];
        sum.x += v0.x; sum.y += v0.y; sum.z += v0.z; sum.w += v0.w;
        mx.x = fmaxf(mx.x, v0.x); mx.y = fmaxf(mx.y, v0.y);
        mx.z = fmaxf(mx.z, v0.z); mx.w = fmaxf(mx.w, v0.w);
        sum.x += v1.x; sum.y += v1.y; sum.z += v1.z; sum.w += v1.w;
        mx.x = fmaxf(mx.x, v1.x); mx.y = fmaxf(mx.y, v1.y);
        mx.z = fmaxf(mx.z, v1.z); mx.w = fmaxf(mx.w, v1.w);
        sum.x += v2.x; sum.y += v2.y; sum.z += v2.z; sum.w += v2.w;
        mx.x = fmaxf(mx.x, v2.x); mx.y = fmaxf(mx.y, v2.y);
        mx.z = fmaxf(mx.z, v2.z); mx.w = fmaxf(mx.w, v2.w);
        sum.x += v3.x; sum.y += v3.y; sum.z += v3.z; sum.w += v3.w;
        mx.x = fmaxf(mx.x, v3.x); mx.y = fmaxf(mx.y, v3.y);
        mx.z = fmaxf(mx.z, v3.z); mx.w = fmaxf(mx.w, v3.w);
    }
    for (; e < end; e++) {
        int s0 = g_perm[e];
        float4 v0 = hv[s0 * 32 + lane];
        sum.x += v0.x; sum.y += v0.y; sum.z += v0.z; sum.w += v0.w;
        mx.x = fmaxf(mx.x, v0.x); mx.y = fmaxf(mx.y, v0.y);
        mx.z = fmaxf(mx.z, v0.z); mx.w = fmaxf(mx.w, v0.w);
    }

    int cnt = end - beg;
    if (cnt == 0) mx = make_float4(0.f, 0.f, 0.f, 0.f);
    float inv = 1.0f / (float)(cnt > 0 ? cnt : 1);
    float4 mean = make_float4(sum.x * inv, sum.y * inv, sum.z * inv, sum.w * inv);

    float4* out = (float4*)(g_agg + (size_t)d * 4 * H);
    const float4* __restrict__ dfv = (const float4*)dst_feat;
    out[lane]       = sum;
    out[32 + lane]  = mx;
    out[64 + lane]  = mean;
    out[96 + lane]  = dfv[d * 32 + lane];
}

// ---------------- fused GEMM (C = epi(A @ W + b) [+ res]) ----------------
#define BM 128
#define BN 128
#define BK 16

// MODE 0: A=param(src_feat), C=g_hidden, lrelu, no residual
// MODE 1: A=g_hidden,        C=g_h,      no lrelu, residual=param(src_feat)
// MODE 2: A=g_agg,           C=param(d_out), lrelu, residual=param(dst_feat)
template <int MODE>
__global__ __launch_bounds__(256) void gemm_kernel(
    const float* __restrict__ Ap, const float* __restrict__ W,
    const float* __restrict__ bias, const float* __restrict__ res,
    float* __restrict__ Cp, int M, int K)
{
    const float* A = (MODE == 1) ? g_hidden : (MODE == 2) ? g_agg : Ap;
    float* C = (MODE == 0) ? g_hidden : (MODE == 1) ? g_h : Cp;
    constexpr bool LRELU = (MODE != 1);
    constexpr bool RESID = (MODE != 0);

    __shared__ float As[2][BK][BM];
    __shared__ float Ws[2][BK][BN];

    int tid = threadIdx.x;
    int block_row = blockIdx.x * BM;
    int tx = tid & 15, ty = tid >> 4;

    int a_row[2], a_col[2], w_k[2], w_n[2];
#pragma unroll
    for (int l = 0; l < 2; l++) {
        int flat = tid + l * 256;
        a_row[l] = flat >> 2;
        a_col[l] = (flat & 3) * 4;
        w_k[l] = flat >> 5;
        w_n[l] = (flat & 31) * 4;
    }

    float4 a_reg[2], w_reg[2];
    int ntiles = K / BK;

    auto fetch = [&](int t) {
#pragma unroll
        for (int l = 0; l < 2; l++) {
            int rg = block_row + a_row[l];
            if (rg < M)
                a_reg[l] = *(const float4*)(A + (size_t)rg * K + t * BK + a_col[l]);
            else
                a_reg[l] = make_float4(0.f, 0.f, 0.f, 0.f);
            w_reg[l] = *(const float4*)(W + (size_t)(t * BK + w_k[l]) * BN + w_n[l]);
        }
    };
    auto stage = [&](int buf) {
#pragma unroll
        for (int l = 0; l < 2; l++) {
            As[buf][a_col[l] + 0][a_row[l]] = a_reg[l].x;
            As[buf][a_col[l] + 1][a_row[l]] = a_reg[l].y;
            As[buf][a_col[l] + 2][a_row[l]] = a_reg[l].z;
            As[buf][a_col[l] + 3][a_row[l]] = a_reg[l].w;
            *(float4*)&Ws[buf][w_k[l]][w_n[l]] = w_reg[l];
        }
    };

    float acc[8][8] = {};
    fetch(0);
    stage(0);
    __syncthreads();

    for (int t = 0; t < ntiles; t++) {
        if (t + 1 < ntiles) fetch(t + 1);
        int buf = t & 1;
#pragma unroll
        for (int k = 0; k < BK; k++) {
            float4 a0 = *(const float4*)&As[buf][k][ty * 8];
            float4 a1 = *(const float4*)&As[buf][k][ty * 8 + 4];
            float4 b0 = *(const float4*)&Ws[buf][k][tx * 8];
            float4 b1 = *(const float4*)&Ws[buf][k][tx * 8 + 4];
            float av[8] = {a0.x, a0.y, a0.z, a0.w, a1.x, a1.y, a1.z, a1.w};
            float bv[8] = {b0.x, b0.y, b0.z, b0.w, b1.x, b1.y, b1.z, b1.w};
#pragma unroll
            for (int i = 0; i < 8; i++)
#pragma unroll
                for (int j = 0; j < 8; j++)
                    acc[i][j] = fmaf(av[i], bv[j], acc[i][j]);
        }
        if (t + 1 < ntiles) stage((t + 1) & 1);
        __syncthreads();
    }

    float bv[8];
#pragma unroll
    for (int j = 0; j < 8; j++) bv[j] = bias[tx * 8 + j];

#pragma unroll
    for (int i = 0; i < 8; i++) {
        int rg = block_row + ty * 8 + i;
        if (rg >= M) continue;
#pragma unroll
        for (int j = 0; j < 8; j++) {
            float v = acc[i][j] + bv[j];
            if (LRELU) v = v > 0.f ? v : 0.1f * v;
            if (RESID) v += res[(size_t)rg * H + tx * 8 + j];
            C[(size_t)rg * H + tx * 8 + j] = v;
        }
    }
}

// ---------------- launch ----------------
extern "C" void kernel_launch(void* const* d_in, const int* in_sizes, int n_in,
                              void* d_out, int out_size) {
    const float* src_feat = (const float*)d_in[0];
    const float* dst_feat = (const float*)d_in[1];
    const int*   edge_src = (const int*)d_in[2];
    const int*   edge_dst = (const int*)d_in[3];
    const float* W1 = (const float*)d_in[4];
    const float* b1 = (const float*)d_in[5];
    const float* W2 = (const float*)d_in[6];
    const float* b2 = (const float*)d_in[7];
    const float* Wr = (const float*)d_in[8];
    const float* br = (const float*)d_in[9];
    float* out = (float*)d_out;

    int n_src = in_sizes[0] / H;
    int n_dst = in_sizes[1] / H;
    int E     = in_sizes[2];

    int gm_src = (n_src + BM - 1) / BM;
    int gm_dst = (n_dst + BM - 1) / BM;
    int nb = (n_dst + 1023) / 1024;

    // One-time side stream + fork/join events (host objects, no device memory).
    static cudaStream_t side = nullptr;
    static cudaEvent_t ev_fork = nullptr, ev_join = nullptr;
    if (!side) {
        cudaStreamCreateWithFlags(&side, cudaStreamNonBlocking);
        cudaEventCreateWithFlags(&ev_fork, cudaEventDisableTiming);
        cudaEventCreateWithFlags(&ev_join, cudaEventDisableTiming);
    }

    // Fork: CSR build on side stream, concurrent with the src MLP GEMMs.
    cudaEventRecord(ev_fork, 0);
    cudaStreamWaitEvent(side, ev_fork, 0);

    zero_cnt_kernel<<<(n_dst + 255) / 256, 256, 0, side>>>(n_dst);
    count_kernel<<<(E + 1023) / 1024, 256, 0, side>>>(edge_dst, E);
    scan_block_kernel<<<nb, 1024, 0, side>>>(n_dst);
    scan_partials_kernel<<<1, 32, 0, side>>>(nb, n_dst);
    scan_add_kernel<<<nb, 1024, 0, side>>>(n_dst);
    scatter_kernel<<<(E + 1023) / 1024, 256, 0, side>>>(edge_src, edge_dst, E);

    cudaEventRecord(ev_join, side);

    // Main stream: src MLP (independent of CSR)
    gemm_kernel<0><<<gm_src, 256>>>(src_feat, W1, b1, nullptr, nullptr, n_src, H);
    gemm_kernel<1><<<gm_src, 256>>>(nullptr, W2, b2, src_feat, nullptr, n_src, H);

    // Join: aggregation needs both g_h and the CSR
    cudaStreamWaitEvent(0, ev_join, 0);

    agg_kernel<<<(n_dst * 32 + 255) / 256, 256>>>(dst_feat, n_dst);

    // readout: out = dst_feat + lrelu(agg @ Wr + br)
    gemm_kernel<2><<<gm_dst, 256>>>(nullptr, Wr, br, dst_feat, out, n_dst, 4 * H);
}

// round 4
// speedup vs baseline: 1.6879x; 1.4836x over previous
#include <cuda_runtime.h>
#include <math.h>

#define H 128
#define MAX_SRC 20000
#define MAX_DST 20000
#define MAX_E   640000

// ---------------- device scratch (no runtime allocation) ----------------
__device__ float g_hidden[MAX_SRC * H];
__device__ float g_h[MAX_SRC * H];
__device__ float g_agg[MAX_DST * 4 * H];
__device__ int   g_cnt[MAX_DST];
__device__ int   g_off[MAX_DST + 1];
__device__ int   g_cursor[MAX_DST];
__device__ int   g_perm[MAX_E];
__device__ int   g_bsum[32];

// ---------------- CSR build ----------------
__global__ void zero_cnt_kernel(int n_dst) {
    int i = blockIdx.x * blockDim.x + threadIdx.x;
    if (i < n_dst) g_cnt[i] = 0;
}

// 4 edges per thread for MLP
__global__ void count_kernel(const int* __restrict__ edge_dst, int E) {
    int i = (blockIdx.x * blockDim.x + threadIdx.x) * 4;
    int d0 = (i + 0 < E) ? edge_dst[i + 0] : -1;
    int d1 = (i + 1 < E) ? edge_dst[i + 1] : -1;
    int d2 = (i + 2 < E) ? edge_dst[i + 2] : -1;
    int d3 = (i + 3 < E) ? edge_dst[i + 3] : -1;
    if (d0 >= 0) atomicAdd(&g_cnt[d0], 1);
    if (d1 >= 0) atomicAdd(&g_cnt[d1], 1);
    if (d2 >= 0) atomicAdd(&g_cnt[d2], 1);
    if (d3 >= 0) atomicAdd(&g_cnt[d3], 1);
}

// phase 1 — block-local exclusive scan + block totals
__global__ void scan_block_kernel(int n) {
    __shared__ int s[1024];
    int tid = threadIdx.x;
    int i = blockIdx.x * 1024 + tid;
    int v = (i < n) ? g_cnt[i] : 0;
    s[tid] = v;
    __syncthreads();
    for (int d = 1; d < 1024; d <<= 1) {
        int t = (tid >= d) ? s[tid - d] : 0;
        __syncthreads();
        s[tid] += t;
        __syncthreads();
    }
    if (i < n) g_off[i] = s[tid] - v;  // block-local exclusive
    if (tid == 1023) g_bsum[blockIdx.x] = s[1023];
}

// phase 2 — each block recomputes the block-prefix (nb<=32) and adds it
__global__ void scan_add_kernel(int nb, int n) {
    __shared__ int pre[33];
    int tid = threadIdx.x;
    if (tid < 32) {
        int v0 = (tid < nb) ? g_bsum[tid] : 0;
        int v = v0;
        for (int d = 1; d < 32; d <<= 1) {
            int t = __shfl_up_sync(0xffffffffu, v, d);
            if (tid >= d) v += t;
        }
        pre[tid] = v - v0;         // exclusive prefix of block sums
        if (tid == 31) pre[32] = v; // grand total
    }
    __syncthreads();
    int i = blockIdx.x * 1024 + tid;
    if (i < n) {
        int o = g_off[i] + pre[blockIdx.x];
        g_off[i] = o;
        g_cursor[i] = o;
    }
    if (blockIdx.x == 0 && tid == 0) g_off[n] = pre[32];
}

// 4 edges per thread for MLP
__global__ void scatter_kernel(const int* __restrict__ edge_src,
                               const int* __restrict__ edge_dst, int E) {
    int i = (blockIdx.x * blockDim.x + threadIdx.x) * 4;
#pragma unroll
    for (int j = 0; j < 4; j++) {
        if (i + j < E) {
            int d = edge_dst[i + j];
            int s = edge_src[i + j];
            int p = atomicAdd(&g_cursor[d], 1);
            g_perm[p] = s;
        }
    }
}

// ---------------- aggregation: warp per dst, atomic-free, 4-way ILP ----------------
__global__ void agg_kernel(const float* __restrict__ dst_feat, int n_dst) {
    int warp = (blockIdx.x * blockDim.x + threadIdx.x) >> 5;
    int lane = threadIdx.x & 31;
    if (warp >= n_dst) return;
    int d = warp;
    int beg = g_off[d], end = g_off[d + 1];
    const float4* __restrict__ hv = (const float4*)g_h;

    float4 sum = make_float4(0.f, 0.f, 0.f, 0.f);
    float4 mx  = make_float4(-3.4e38f, -3.4e38f, -3.4e38f, -3.4e38f);

    int e = beg;
    for (; e + 3 < end; e += 4) {
        int s0 = g_perm[e];
        int s1 = g_perm[e + 1];
        int s2 = g_perm[e + 2];
        int s3 = g_perm[e + 3];
        float4 v0 = hv[s0 * 32 + lane];
        float4 v1 = hv[s1 * 32 + lane];
        float4 v2 = hv[s2 * 32 + lane];
        float4 v3 = hv[s3 * 32 + lane];
        sum.x += v0.x; sum.y += v0.y; sum.z += v0.z; sum.w += v0.w;
        mx.x = fmaxf(mx.x, v0.x); mx.y = fmaxf(mx.y, v0.y);
        mx.z = fmaxf(mx.z, v0.z); mx.w = fmaxf(mx.w, v0.w);
        sum.x += v1.x; sum.y += v1.y; sum.z += v1.z; sum.w += v1.w;
        mx.x = fmaxf(mx.x, v1.x); mx.y = fmaxf(mx.y, v1.y);
        mx.z = fmaxf(mx.z, v1.z); mx.w = fmaxf(mx.w, v1.w);
        sum.x += v2.x; sum.y += v2.y; sum.z += v2.z; sum.w += v2.w;
        mx.x = fmaxf(mx.x, v2.x); mx.y = fmaxf(mx.y, v2.y);
        mx.z = fmaxf(mx.z, v2.z); mx.w = fmaxf(mx.w, v2.w);
        sum.x += v3.x; sum.y += v3.y; sum.z += v3.z; sum.w += v3.w;
        mx.x = fmaxf(mx.x, v3.x); mx.y = fmaxf(mx.y, v3.y);
        mx.z = fmaxf(mx.z, v3.z); mx.w = fmaxf(mx.w, v3.w);
    }
    for (; e < end; e++) {
        int s0 = g_perm[e];
        float4 v0 = hv[s0 * 32 + lane];
        sum.x += v0.x; sum.y += v0.y; sum.z += v0.z; sum.w += v0.w;
        mx.x = fmaxf(mx.x, v0.x); mx.y = fmaxf(mx.y, v0.y);
        mx.z = fmaxf(mx.z, v0.z); mx.w = fmaxf(mx.w, v0.w);
    }

    int cnt = end - beg;
    if (cnt == 0) mx = make_float4(0.f, 0.f, 0.f, 0.f);
    float inv = 1.0f / (float)(cnt > 0 ? cnt : 1);
    float4 mean = make_float4(sum.x * inv, sum.y * inv, sum.z * inv, sum.w * inv);

    float4* out = (float4*)(g_agg + (size_t)d * 4 * H);
    const float4* __restrict__ dfv = (const float4*)dst_feat;
    out[lane]       = sum;
    out[32 + lane]  = mx;
    out[64 + lane]  = mean;
    out[96 + lane]  = dfv[d * 32 + lane];
}

// ---------------- fused GEMM (C = epi(A @ W + b) [+ res]) ----------------
// BM=144 so grid = ceil(20000/144) = 139 <= 148 SMs: exactly one wave,
// one CTA per SM, no wave-quantization tail. 288 threads (18x16), 8x8/thread.
#define BM 144
#define BN 128
#define BK 16
#define NTHREADS 288

// MODE 0: A=param(src_feat), C=g_hidden, lrelu, no residual
// MODE 1: A=g_hidden,        C=g_h,      no lrelu, residual=param(src_feat)
// MODE 2: A=g_agg,           C=param(d_out), lrelu, residual=param(dst_feat)
template <int MODE>
__global__ __launch_bounds__(NTHREADS, 1) void gemm_kernel(
    const float* __restrict__ Ap, const float* __restrict__ W,
    const float* __restrict__ bias, const float* __restrict__ res,
    float* __restrict__ Cp, int M, int K)
{
    const float* A = (MODE == 1) ? g_hidden : (MODE == 2) ? g_agg : Ap;
    float* C = (MODE == 0) ? g_hidden : (MODE == 1) ? g_h : Cp;
    constexpr bool LRELU = (MODE != 1);
    constexpr bool RESID = (MODE != 0);

    __shared__ float As[2][BK][BM];   // 2*16*144*4 = 18432 B
    __shared__ float Ws[2][BK][BN];   // 2*16*128*4 = 16384 B

    int tid = threadIdx.x;
    int block_row = blockIdx.x * BM;
    int tx = tid & 15, ty = tid >> 4;   // tx 0..15, ty 0..17

    // A tile: BM*BK = 2304 floats = 576 float4; 288 threads -> 2 each.
    // W tile: BK*BN = 2048 floats = 512 float4; threads with flat<512 load.
    int a_row[2], a_col[2], w_k[2], w_n[2];
    bool w_ok[2];
#pragma unroll
    for (int l = 0; l < 2; l++) {
        int flat = tid + l * NTHREADS;
        a_row[l] = flat >> 2;          // 0..575>>2 = 0..143
        a_col[l] = (flat & 3) * 4;
        w_ok[l] = flat < 512;
        int wf = w_ok[l] ? flat : 0;
        w_k[l] = wf >> 5;
        w_n[l] = (wf & 31) * 4;
    }

    float4 a_reg[2], w_reg[2];
    int ntiles = K / BK;

    auto fetch = [&](int t) {
#pragma unroll
        for (int l = 0; l < 2; l++) {
            int rg = block_row + a_row[l];
            if (rg < M)
                a_reg[l] = *(const float4*)(A + (size_t)rg * K + t * BK + a_col[l]);
            else
                a_reg[l] = make_float4(0.f, 0.f, 0.f, 0.f);
            if (w_ok[l])
                w_reg[l] = *(const float4*)(W + (size_t)(t * BK + w_k[l]) * BN + w_n[l]);
        }
    };
    auto stage = [&](int buf) {
#pragma unroll
        for (int l = 0; l < 2; l++) {
            As[buf][a_col[l] + 0][a_row[l]] = a_reg[l].x;
            As[buf][a_col[l] + 1][a_row[l]] = a_reg[l].y;
            As[buf][a_col[l] + 2][a_row[l]] = a_reg[l].z;
            As[buf][a_col[l] + 3][a_row[l]] = a_reg[l].w;
            if (w_ok[l])
                *(float4*)&Ws[buf][w_k[l]][w_n[l]] = w_reg[l];
        }
    };

    float acc[8][8] = {};
    fetch(0);
    stage(0);
    __syncthreads();

    for (int t = 0; t < ntiles; t++) {
        if (t + 1 < ntiles) fetch(t + 1);
        int buf = t & 1;
#pragma unroll
        for (int k = 0; k < BK; k++) {
            float4 a0 = *(const float4*)&As[buf][k][ty * 8];
            float4 a1 = *(const float4*)&As[buf][k][ty * 8 + 4];
            float4 b0 = *(const float4*)&Ws[buf][k][tx * 8];
            float4 b1 = *(const float4*)&Ws[buf][k][tx * 8 + 4];
            float av[8] = {a0.x, a0.y, a0.z, a0.w, a1.x, a1.y, a1.z, a1.w};
            float bv[8] = {b0.x, b0.y, b0.z, b0.w, b1.x, b1.y, b1.z, b1.w};
#pragma unroll
            for (int i = 0; i < 8; i++)
#pragma unroll
                for (int j = 0; j < 8; j++)
                    acc[i][j] = fmaf(av[i], bv[j], acc[i][j]);
        }
        if (t + 1 < ntiles) stage((t + 1) & 1);
        __syncthreads();
    }

    float bv[8];
#pragma unroll
    for (int j = 0; j < 8; j++) bv[j] = bias[tx * 8 + j];

#pragma unroll
    for (int i = 0; i < 8; i++) {
        int rg = block_row + ty * 8 + i;
        if (rg >= M) continue;
#pragma unroll
        for (int j = 0; j < 8; j++) {
            float v = acc[i][j] + bv[j];
            if (LRELU) v = v > 0.f ? v : 0.1f * v;
            if (RESID) v += res[(size_t)rg * H + tx * 8 + j];
            C[(size_t)rg * H + tx * 8 + j] = v;
        }
    }
}

// ---------------- launch ----------------
extern "C" void kernel_launch(void* const* d_in, const int* in_sizes, int n_in,
                              void* d_out, int out_size) {
    const float* src_feat = (const float*)d_in[0];
    const float* dst_feat = (const float*)d_in[1];
    const int*   edge_src = (const int*)d_in[2];
    const int*   edge_dst = (const int*)d_in[3];
    const float* W1 = (const float*)d_in[4];
    const float* b1 = (const float*)d_in[5];
    const float* W2 = (const float*)d_in[6];
    const float* b2 = (const float*)d_in[7];
    const float* Wr = (const float*)d_in[8];
    const float* br = (const float*)d_in[9];
    float* out = (float*)d_out;

    int n_src = in_sizes[0] / H;
    int n_dst = in_sizes[1] / H;
    int E     = in_sizes[2];

    int gm_src = (n_src + BM - 1) / BM;   // 139
    int gm_dst = (n_dst + BM - 1) / BM;   // 139
    int nb = (n_dst + 1023) / 1024;

    // One-time side stream + fork/join events (host objects, no device memory).
    static cudaStream_t side = nullptr;
    static cudaEvent_t ev_fork = nullptr, ev_join = nullptr;
    if (!side) {
        cudaStreamCreateWithFlags(&side, cudaStreamNonBlocking);
        cudaEventCreateWithFlags(&ev_fork, cudaEventDisableTiming);
        cudaEventCreateWithFlags(&ev_join, cudaEventDisableTiming);
    }

    // Fork: CSR build on side stream, concurrent with the src MLP GEMMs.
    cudaEventRecord(ev_fork, 0);
    cudaStreamWaitEvent(side, ev_fork, 0);

    zero_cnt_kernel<<<(n_dst + 255) / 256, 256, 0, side>>>(n_dst);
    count_kernel<<<(E + 1023) / 1024, 256, 0, side>>>(edge_dst, E);
    scan_block_kernel<<<nb, 1024, 0, side>>>(n_dst);
    scan_add_kernel<<<nb, 1024, 0, side>>>(nb, n_dst);
    scatter_kernel<<<(E + 1023) / 1024, 256, 0, side>>>(edge_src, edge_dst, E);

    cudaEventRecord(ev_join, side);

    // Main stream: src MLP (independent of CSR)
    gemm_kernel<0><<<gm_src, NTHREADS>>>(src_feat, W1, b1, nullptr, nullptr, n_src, H);
    gemm_kernel<1><<<gm_src, NTHREADS>>>(nullptr, W2, b2, src_feat, nullptr, n_src, H);

    // Join: aggregation needs both g_h and the CSR
    cudaStreamWaitEvent(0, ev_join, 0);

    agg_kernel<<<(n_dst * 32 + 255) / 256, 256>>>(dst_feat, n_dst);

    // readout: out = dst_feat + lrelu(agg @ Wr + br)
    gemm_kernel<2><<<gm_dst, NTHREADS>>>(nullptr, Wr, br, dst_feat, out, n_dst, 4 * H);
}

// round 8
// speedup vs baseline: 1.7683x; 1.0477x over previous
#include <cuda_runtime.h>
#include <math.h>

#define H 128
#define MAX_SRC 20000
#define MAX_DST 20000
#define MAX_E   640000

// ---------------- device scratch (no runtime allocation) ----------------
__device__ float g_h[MAX_SRC * H];
__device__ float g_agg[MAX_DST * 4 * H];
__device__ int   g_cnt[MAX_DST];
__device__ int   g_off[MAX_DST + 1];
__device__ int   g_cursor[MAX_DST];
__device__ int   g_perm[MAX_E];
__device__ int   g_bsum[32];

// ---------------- CSR build ----------------
__global__ void zero_cnt_kernel(int n_dst) {
    int i = blockIdx.x * blockDim.x + threadIdx.x;
    if (i < n_dst) g_cnt[i] = 0;
}

// int4 vector loads, 4 edges/thread
__global__ void count_kernel(const int* __restrict__ edge_dst, int E) {
    int i = (blockIdx.x * blockDim.x + threadIdx.x) * 4;
    if (i + 3 < E) {
        int4 d = *(const int4*)(edge_dst + i);
        atomicAdd(&g_cnt[d.x], 1);
        atomicAdd(&g_cnt[d.y], 1);
        atomicAdd(&g_cnt[d.z], 1);
        atomicAdd(&g_cnt[d.w], 1);
    } else {
        for (int j = 0; j < 4 && i + j < E; j++)
            atomicAdd(&g_cnt[edge_dst[i + j]], 1);
    }
}

// phase 1 — block-local exclusive scan (warp-shuffle) + block totals
__global__ void scan_block_kernel(int n) {
    __shared__ int warp_sums[32];
    int tid = threadIdx.x, lane = tid & 31, wid = tid >> 5;
    int i = blockIdx.x * 1024 + tid;
    int v = (i < n) ? g_cnt[i] : 0;
    int x = v;
#pragma unroll
    for (int d = 1; d < 32; d <<= 1) {
        int t = __shfl_up_sync(0xffffffffu, x, d);
        if (lane >= d) x += t;
    }
    if (lane == 31) warp_sums[wid] = x;
    __syncthreads();
    if (wid == 0) {
        int s = warp_sums[lane];
#pragma unroll
        for (int d = 1; d < 32; d <<= 1) {
            int t = __shfl_up_sync(0xffffffffu, s, d);
            if (lane >= d) s += t;
        }
        warp_sums[lane] = s;
    }
    __syncthreads();
    int warp_pre = (wid == 0) ? 0 : warp_sums[wid - 1];
    int incl = warp_pre + x;
    if (i < n) g_off[i] = incl - v;            // block-local exclusive
    if (tid == 1023) g_bsum[blockIdx.x] = incl; // block total
}

// phase 2 — each block recomputes block-prefix (nb<=32) and adds it
__global__ void scan_add_kernel(int nb, int n) {
    __shared__ int pre[33];
    int tid = threadIdx.x;
    if (tid < 32) {
        int v0 = (tid < nb) ? g_bsum[tid] : 0;
        int v = v0;
#pragma unroll
        for (int d = 1; d < 32; d <<= 1) {
            int t = __shfl_up_sync(0xffffffffu, v, d);
            if (tid >= d) v += t;
        }
        pre[tid] = v - v0;
        if (tid == 31) pre[32] = v;
    }
    __syncthreads();
    int i = blockIdx.x * 1024 + tid;
    if (i < n) {
        int o = g_off[i] + pre[blockIdx.x];
        g_off[i] = o;
        g_cursor[i] = o;
    }
    if (blockIdx.x == 0 && tid == 0) g_off[n] = pre[32];
}

// int4 vector loads, 4 edges/thread
__global__ void scatter_kernel(const int* __restrict__ edge_src,
                               const int* __restrict__ edge_dst, int E) {
    int i = (blockIdx.x * blockDim.x + threadIdx.x) * 4;
    if (i + 3 < E) {
        int4 d = *(const int4*)(edge_dst + i);
        int4 s = *(const int4*)(edge_src + i);
        g_perm[atomicAdd(&g_cursor[d.x], 1)] = s.x;
        g_perm[atomicAdd(&g_cursor[d.y], 1)] = s.y;
        g_perm[atomicAdd(&g_cursor[d.z], 1)] = s.z;
        g_perm[atomicAdd(&g_cursor[d.w], 1)] = s.w;
    } else {
        for (int j = 0; j < 4 && i + j < E; j++) {
            int d = edge_dst[i + j];
            int p = atomicAdd(&g_cursor[d], 1);
            g_perm[p] = edge_src[i + j];
        }
    }
}

// ---------------- aggregation: warp per dst, atomic-free, 8-way ILP ----------------
__global__ void agg_kernel(const float* __restrict__ dst_feat, int n_dst) {
    int warp = (blockIdx.x * blockDim.x + threadIdx.x) >> 5;
    int lane = threadIdx.x & 31;
    if (warp >= n_dst) return;
    int d = warp;
    int beg = g_off[d], end = g_off[d + 1];
    const float4* __restrict__ hv = (const float4*)g_h;

    float4 sum = make_float4(0.f, 0.f, 0.f, 0.f);
    float4 mx  = make_float4(-3.4e38f, -3.4e38f, -3.4e38f, -3.4e38f);

    int e = beg;
    for (; e + 7 < end; e += 8) {
        int s[8];
#pragma unroll
        for (int j = 0; j < 8; j++) s[j] = g_perm[e + j];
        float4 v[8];
#pragma unroll
        for (int j = 0; j < 8; j++) v[j] = hv[s[j] * 32 + lane];
#pragma unroll
        for (int j = 0; j < 8; j++) {
            sum.x += v[j].x; sum.y += v[j].y; sum.z += v[j].z; sum.w += v[j].w;
            mx.x = fmaxf(mx.x, v[j].x); mx.y = fmaxf(mx.y, v[j].y);
            mx.z = fmaxf(mx.z, v[j].z); mx.w = fmaxf(mx.w, v[j].w);
        }
    }
    for (; e < end; e++) {
        int s0 = g_perm[e];
        float4 v0 = hv[s0 * 32 + lane];
        sum.x += v0.x; sum.y += v0.y; sum.z += v0.z; sum.w += v0.w;
        mx.x = fmaxf(mx.x, v0.x); mx.y = fmaxf(mx.y, v0.y);
        mx.z = fmaxf(mx.z, v0.z); mx.w = fmaxf(mx.w, v0.w);
    }

    int cnt = end - beg;
    if (cnt == 0) mx = make_float4(0.f, 0.f, 0.f, 0.f);
    float inv = 1.0f / (float)(cnt > 0 ? cnt : 1);
    float4 mean = make_float4(sum.x * inv, sum.y * inv, sum.z * inv, sum.w * inv);

    float4* out = (float4*)(g_agg + (size_t)d * 4 * H);
    const float4* __restrict__ dfv = (const float4*)dst_feat;
    out[lane]       = sum;
    out[32 + lane]  = mx;
    out[64 + lane]  = mean;
    out[96 + lane]  = dfv[d * 32 + lane];
}

// ---------------- tiling constants ----------------
#define BM 144
#define BN 128
#define BK 16
#define NTHREADS 288
#define HS_PAD 136   // Hs row stride in floats; %4==0 so float4-aligned rows

// ---------------- fused MLP: h = src + lrelu(src@W1+b1)@W2 + b2 ----------------
// One block = 144 rows. Phase 1 computes the hidden tile into smem row-major
// Hs[row][k] (float4 stores, aligned). Phase 2 reads A as scalar broadcast
// loads Hs[row][kk] (16 lanes share each address -> free broadcast).
__global__ __launch_bounds__(NTHREADS, 1) void mlp_fused_kernel(
    const float* __restrict__ src, const float* __restrict__ W1,
    const float* __restrict__ b1, const float* __restrict__ W2,
    const float* __restrict__ b2, int M)
{
    extern __shared__ float smem[];
    float* Ws = smem;                       // [2][BK][BN] = 4096 floats
    float* As = smem + 4096;                // [2][BK][BM] = 4608 floats
    float* Hs = smem + 4096 + 4608;         // [BM][HS_PAD] = 19584 floats

    int tid = threadIdx.x;
    int block_row = blockIdx.x * BM;
    int tx = tid & 15, ty = tid >> 4;

    int a_row[2], a_col[2], w_k[2], w_n[2];
    bool w_ok[2];
#pragma unroll
    for (int l = 0; l < 2; l++) {
        int flat = tid + l * NTHREADS;
        a_row[l] = flat >> 2;
        a_col[l] = (flat & 3) * 4;
        w_ok[l] = flat < 512;
        int wf = w_ok[l] ? flat : 0;
        w_k[l] = wf >> 5;
        w_n[l] = (wf & 31) * 4;
    }

    float4 a_reg[2], w_reg[2];
    const int ntiles = H / BK;  // 8

    // ---------- phase 1: hidden = lrelu(src@W1 + b1) ----------
    {
        auto fetch = [&](int t) {
#pragma unroll
            for (int l = 0; l < 2; l++) {
                int rg = block_row + a_row[l];
                a_reg[l] = (rg < M) ? *(const float4*)(src + (size_t)rg * H + t * BK + a_col[l])
                                    : make_float4(0.f, 0.f, 0.f, 0.f);
                if (w_ok[l])
                    w_reg[l] = *(const float4*)(W1 + (size_t)(t * BK + w_k[l]) * BN + w_n[l]);
            }
        };
        auto stage = [&](int buf) {
#pragma unroll
            for (int l = 0; l < 2; l++) {
                float* Ab = As + buf * (BK * BM);
                Ab[(a_col[l] + 0) * BM + a_row[l]] = a_reg[l].x;
                Ab[(a_col[l] + 1) * BM + a_row[l]] = a_reg[l].y;
                Ab[(a_col[l] + 2) * BM + a_row[l]] = a_reg[l].z;
                Ab[(a_col[l] + 3) * BM + a_row[l]] = a_reg[l].w;
                if (w_ok[l])
                    *(float4*)(Ws + buf * (BK * BN) + w_k[l] * BN + w_n[l]) = w_reg[l];
            }
        };

        float acc[8][8] = {};
        fetch(0); stage(0);
        __syncthreads();
        for (int t = 0; t < ntiles; t++) {
            if (t + 1 < ntiles) fetch(t + 1);
            const float* Ab = As + (t & 1) * (BK * BM);
            const float* Wb = Ws + (t & 1) * (BK * BN);
#pragma unroll
            for (int k = 0; k < BK; k++) {
                float4 a0 = *(const float4*)(Ab + k * BM + ty * 8);
                float4 a1 = *(const float4*)(Ab + k * BM + ty * 8 + 4);
                float4 c0 = *(const float4*)(Wb + k * BN + tx * 8);
                float4 c1 = *(const float4*)(Wb + k * BN + tx * 8 + 4);
                float av[8] = {a0.x, a0.y, a0.z, a0.w, a1.x, a1.y, a1.z, a1.w};
                float bv[8] = {c0.x, c0.y, c0.z, c0.w, c1.x, c1.y, c1.z, c1.w};
#pragma unroll
                for (int i = 0; i < 8; i++)
#pragma unroll
                    for (int j = 0; j < 8; j++)
                        acc[i][j] = fmaf(av[i], bv[j], acc[i][j]);
            }
            if (t + 1 < ntiles) stage((t + 1) & 1);
            __syncthreads();
        }

        // epilogue: lrelu + bias, float4 stores into Hs[row][k] (k = tx*8+j)
        float bv[8];
#pragma unroll
        for (int j = 0; j < 8; j++) bv[j] = b1[tx * 8 + j];
#pragma unroll
        for (int i = 0; i < 8; i++) {
            float v[8];
#pragma unroll
            for (int j = 0; j < 8; j++) {
                float t = acc[i][j] + bv[j];
                v[j] = t > 0.f ? t : 0.1f * t;
            }
            float* row = Hs + (ty * 8 + i) * HS_PAD + tx * 8;
            *(float4*)(row)     = make_float4(v[0], v[1], v[2], v[3]);
            *(float4*)(row + 4) = make_float4(v[4], v[5], v[6], v[7]);
        }
    }
    __syncthreads();

    // ---------- phase 2: h = src + hidden@W2 + b2 ----------
    {
        auto fetchW = [&](int t) {
#pragma unroll
            for (int l = 0; l < 2; l++)
                if (w_ok[l])
                    w_reg[l] = *(const float4*)(W2 + (size_t)(t * BK + w_k[l]) * BN + w_n[l]);
        };
        auto stageW = [&](int buf) {
#pragma unroll
            for (int l = 0; l < 2; l++)
                if (w_ok[l])
                    *(float4*)(Ws + buf * (BK * BN) + w_k[l] * BN + w_n[l]) = w_reg[l];
        };

        float acc[8][8] = {};
        fetchW(0); stageW(0);
        __syncthreads();
        for (int t = 0; t < ntiles; t++) {
            if (t + 1 < ntiles) fetchW(t + 1);
            const float* Wb = Ws + (t & 1) * (BK * BN);
#pragma unroll
            for (int k = 0; k < BK; k++) {
                int kk = t * BK + k;
                float av[8];
#pragma unroll
                for (int i = 0; i < 8; i++)
                    av[i] = Hs[(ty * 8 + i) * HS_PAD + kk];  // broadcast across tx
                float4 c0 = *(const float4*)(Wb + k * BN + tx * 8);
                float4 c1 = *(const float4*)(Wb + k * BN + tx * 8 + 4);
                float bv[8] = {c0.x, c0.y, c0.z, c0.w, c1.x, c1.y, c1.z, c1.w};
#pragma unroll
                for (int i = 0; i < 8; i++)
#pragma unroll
                    for (int j = 0; j < 8; j++)
                        acc[i][j] = fmaf(av[i], bv[j], acc[i][j]);
            }
            if (t + 1 < ntiles) stageW((t + 1) & 1);
            __syncthreads();
        }

        float bv[8];
#pragma unroll
        for (int j = 0; j < 8; j++) bv[j] = b2[tx * 8 + j];
#pragma unroll
        for (int i = 0; i < 8; i++) {
            int rg = block_row + ty * 8 + i;
            if (rg >= M) continue;
#pragma unroll
            for (int j = 0; j < 8; j++) {
                float v = acc[i][j] + bv[j] + src[(size_t)rg * H + tx * 8 + j];
                g_h[(size_t)rg * H + tx * 8 + j] = v;
            }
        }
    }
}

// ---------------- readout GEMM (C = res + lrelu(A @ W + b)) ----------------
__global__ __launch_bounds__(NTHREADS, 1) void gemm2_kernel(
    const float* __restrict__ W, const float* __restrict__ bias,
    const float* __restrict__ res, float* __restrict__ C, int M, int K)
{
    const float* A = g_agg;

    __shared__ float As[2][BK][BM];
    __shared__ float Ws[2][BK][BN];

    int tid = threadIdx.x;
    int block_row = blockIdx.x * BM;
    int tx = tid & 15, ty = tid >> 4;

    int a_row[2], a_col[2], w_k[2], w_n[2];
    bool w_ok[2];
#pragma unroll
    for (int l = 0; l < 2; l++) {
        int flat = tid + l * NTHREADS;
        a_row[l] = flat >> 2;
        a_col[l] = (flat & 3) * 4;
        w_ok[l] = flat < 512;
        int wf = w_ok[l] ? flat : 0;
        w_k[l] = wf >> 5;
        w_n[l] = (wf & 31) * 4;
    }

    float4 a_reg[2], w_reg[2];
    int ntiles = K / BK;

    auto fetch = [&](int t) {
#pragma unroll
        for (int l = 0; l < 2; l++) {
            int rg = block_row + a_row[l];
            a_reg[l] = (rg < M) ? *(const float4*)(A + (size_t)rg * K + t * BK + a_col[l])
                                : make_float4(0.f, 0.f, 0.f, 0.f);
            if (w_ok[l])
                w_reg[l] = *(const float4*)(W + (size_t)(t * BK + w_k[l]) * BN + w_n[l]);
        }
    };
    auto stage = [&](int buf) {
#pragma unroll
        for (int l = 0; l < 2; l++) {
            As[buf][a_col[l] + 0][a_row[l]] = a_reg[l].x;
            As[buf][a_col[l] + 1][a_row[l]] = a_reg[l].y;
            As[buf][a_col[l] + 2][a_row[l]] = a_reg[l].z;
            As[buf][a_col[l] + 3][a_row[l]] = a_reg[l].w;
            if (w_ok[l])
                *(float4*)&Ws[buf][w_k[l]][w_n[l]] = w_reg[l];
        }
    };

    float acc[8][8] = {};
    fetch(0); stage(0);
    __syncthreads();

    for (int t = 0; t < ntiles; t++) {
        if (t + 1 < ntiles) fetch(t + 1);
        int buf = t & 1;
#pragma unroll
        for (int k = 0; k < BK; k++) {
            float4 a0 = *(const float4*)&As[buf][k][ty * 8];
            float4 a1 = *(const float4*)&As[buf][k][ty * 8 + 4];
            float4 c0 = *(const float4*)&Ws[buf][k][tx * 8];
            float4 c1 = *(const float4*)&Ws[buf][k][tx * 8 + 4];
            float av[8] = {a0.x, a0.y, a0.z, a0.w, a1.x, a1.y, a1.z, a1.w};
            float bv[8] = {c0.x, c0.y, c0.z, c0.w, c1.x, c1.y, c1.z, c1.w};
#pragma unroll
            for (int i = 0; i < 8; i++)
#pragma unroll
                for (int j = 0; j < 8; j++)
                    acc[i][j] = fmaf(av[i], bv[j], acc[i][j]);
        }
        if (t + 1 < ntiles) stage((t + 1) & 1);
        __syncthreads();
    }

    float bv[8];
#pragma unroll
    for (int j = 0; j < 8; j++) bv[j] = bias[tx * 8 + j];

#pragma unroll
    for (int i = 0; i < 8; i++) {
        int rg = block_row + ty * 8 + i;
        if (rg >= M) continue;
#pragma unroll
        for (int j = 0; j < 8; j++) {
            float v = acc[i][j] + bv[j];
            v = v > 0.f ? v : 0.1f * v;
            v += res[(size_t)rg * H + tx * 8 + j];
            C[(size_t)rg * H + tx * 8 + j] = v;
        }
    }
}

// ---------------- launch ----------------
extern "C" void kernel_launch(void* const* d_in, const int* in_sizes, int n_in,
                              void* d_out, int out_size) {
    const float* src_feat = (const float*)d_in[0];
    const float* dst_feat = (const float*)d_in[1];
    const int*   edge_src = (const int*)d_in[2];
    const int*   edge_dst = (const int*)d_in[3];
    const float* W1 = (const float*)d_in[4];
    const float* b1 = (const float*)d_in[5];
    const float* W2 = (const float*)d_in[6];
    const float* b2 = (const float*)d_in[7];
    const float* Wr = (const float*)d_in[8];
    const float* br = (const float*)d_in[9];
    float* out = (float*)d_out;

    int n_src = in_sizes[0] / H;
    int n_dst = in_sizes[1] / H;
    int E     = in_sizes[2];

    int gm_src = (n_src + BM - 1) / BM;   // 139
    int gm_dst = (n_dst + BM - 1) / BM;   // 139
    int nb = (n_dst + 1023) / 1024;

    size_t mlp_smem = (size_t)(4096 + 4608 + BM * HS_PAD) * 4;  // 110,592 B

    // One-time stream/event/attribute setup (host objects only).
    static cudaStream_t side = nullptr;
    static cudaEvent_t ev_fork = nullptr, ev_join = nullptr;
    if (!side) {
        cudaStreamCreateWithFlags(&side, cudaStreamNonBlocking);
        cudaEventCreateWithFlags(&ev_fork, cudaEventDisableTiming);
        cudaEventCreateWithFlags(&ev_join, cudaEventDisableTiming);
        cudaFuncSetAttribute(mlp_fused_kernel,
                             cudaFuncAttributeMaxDynamicSharedMemorySize,
                             (int)mlp_smem);
    }

    // Fork: CSR build on side stream, concurrent with the fused MLP.
    cudaEventRecord(ev_fork, 0);
    cudaStreamWaitEvent(side, ev_fork, 0);

    zero_cnt_kernel<<<(n_dst + 255) / 256, 256, 0, side>>>(n_dst);
    count_kernel<<<(E + 1023) / 1024, 256, 0, side>>>(edge_dst, E);
    scan_block_kernel<<<nb, 1024, 0, side>>>(n_dst);
    scan_add_kernel<<<nb, 1024, 0, side>>>(nb, n_dst);
    scatter_kernel<<<(E + 1023) / 1024, 256, 0, side>>>(edge_src, edge_dst, E);

    cudaEventRecord(ev_join, side);

    // Main stream: fused src MLP
    mlp_fused_kernel<<<gm_src, NTHREADS, mlp_smem>>>(src_feat, W1, b1, W2, b2, n_src);

    // Join: aggregation needs both g_h and the CSR
    cudaStreamWaitEvent(0, ev_join, 0);

    agg_kernel<<<(n_dst * 32 + 255) / 256, 256>>>(dst_feat, n_dst);

    // readout: out = dst_feat + lrelu(agg @ Wr + br)
    gemm2_kernel<<<gm_dst, NTHREADS>>>(Wr, br, dst_feat, out, n_dst, 4 * H);
}

// round 10
// speedup vs baseline: 1.8258x; 1.0325x over previous
#include <cuda_runtime.h>
#include <cuda_bf16.h>
#include <math.h>

#define H 128
#define MAX_SRC 20000
#define MAX_DST 20000
#define MAX_E   640000

// ---------------- device scratch (no runtime allocation) ----------------
__device__ float g_h[MAX_SRC * H];
__device__ float g_agg[MAX_DST * 4 * H];
__device__ int   g_cnt[MAX_DST];
__device__ int   g_off[MAX_DST + 1];
__device__ int   g_cursor[MAX_DST];
__device__ int   g_perm[MAX_E];
__device__ int   g_bsum[32];
// W_readout transposed + bf16 hi/lo split: Wt[n][k], n=0..127, k=0..511
__device__ __align__(16) unsigned short g_wt_hi[128 * 512];
__device__ __align__(16) unsigned short g_wt_lo[128 * 512];

// ---------------- small helpers ----------------
__device__ __forceinline__ unsigned short f2bf(float x) {
    __nv_bfloat16 h = __float2bfloat16_rn(x);
    return *reinterpret_cast<unsigned short*>(&h);
}
__device__ __forceinline__ float bf2f(unsigned short u) {
    __nv_bfloat16 h = *reinterpret_cast<__nv_bfloat16*>(&u);
    return __bfloat162float(h);
}

// ---------------- CSR build ----------------
__global__ void zero_cnt_kernel(int n_dst) {
    int i = blockIdx.x * blockDim.x + threadIdx.x;
    if (i < n_dst) g_cnt[i] = 0;
}

__global__ void count_kernel(const int* __restrict__ edge_dst, int E) {
    int i = (blockIdx.x * blockDim.x + threadIdx.x) * 4;
    if (i + 3 < E) {
        int4 d = *(const int4*)(edge_dst + i);
        atomicAdd(&g_cnt[d.x], 1);
        atomicAdd(&g_cnt[d.y], 1);
        atomicAdd(&g_cnt[d.z], 1);
        atomicAdd(&g_cnt[d.w], 1);
    } else {
        for (int j = 0; j < 4 && i + j < E; j++)
            atomicAdd(&g_cnt[edge_dst[i + j]], 1);
    }
}

__global__ void scan_block_kernel(int n) {
    __shared__ int warp_sums[32];
    int tid = threadIdx.x, lane = tid & 31, wid = tid >> 5;
    int i = blockIdx.x * 1024 + tid;
    int v = (i < n) ? g_cnt[i] : 0;
    int x = v;
#pragma unroll
    for (int d = 1; d < 32; d <<= 1) {
        int t = __shfl_up_sync(0xffffffffu, x, d);
        if (lane >= d) x += t;
    }
    if (lane == 31) warp_sums[wid] = x;
    __syncthreads();
    if (wid == 0) {
        int s = warp_sums[lane];
#pragma unroll
        for (int d = 1; d < 32; d <<= 1) {
            int t = __shfl_up_sync(0xffffffffu, s, d);
            if (lane >= d) s += t;
        }
        warp_sums[lane] = s;
    }
    __syncthreads();
    int warp_pre = (wid == 0) ? 0 : warp_sums[wid - 1];
    int incl = warp_pre + x;
    if (i < n) g_off[i] = incl - v;
    if (tid == 1023) g_bsum[blockIdx.x] = incl;
}

__global__ void scan_add_kernel(int nb, int n) {
    __shared__ int pre[33];
    int tid = threadIdx.x;
    if (tid < 32) {
        int v0 = (tid < nb) ? g_bsum[tid] : 0;
        int v = v0;
#pragma unroll
        for (int d = 1; d < 32; d <<= 1) {
            int t = __shfl_up_sync(0xffffffffu, v, d);
            if (tid >= d) v += t;
        }
        pre[tid] = v - v0;
        if (tid == 31) pre[32] = v;
    }
    __syncthreads();
    int i = blockIdx.x * 1024 + tid;
    if (i < n) {
        int o = g_off[i] + pre[blockIdx.x];
        g_off[i] = o;
        g_cursor[i] = o;
    }
    if (blockIdx.x == 0 && tid == 0) g_off[n] = pre[32];
}

__global__ void scatter_kernel(const int* __restrict__ edge_src,
                               const int* __restrict__ edge_dst, int E) {
    int i = (blockIdx.x * blockDim.x + threadIdx.x) * 4;
    if (i + 3 < E) {
        int4 d = *(const int4*)(edge_dst + i);
        int4 s = *(const int4*)(edge_src + i);
        g_perm[atomicAdd(&g_cursor[d.x], 1)] = s.x;
        g_perm[atomicAdd(&g_cursor[d.y], 1)] = s.y;
        g_perm[atomicAdd(&g_cursor[d.z], 1)] = s.z;
        g_perm[atomicAdd(&g_cursor[d.w], 1)] = s.w;
    } else {
        for (int j = 0; j < 4 && i + j < E; j++) {
            int d = edge_dst[i + j];
            int p = atomicAdd(&g_cursor[d], 1);
            g_perm[p] = edge_src[i + j];
        }
    }
}

// ---------------- W-transpose + bf16 hi/lo prep ----------------
// Wt_hi/lo[n][k] = split(Wr[k][n]); Wr is [512,128] row-major.
__global__ void wt_prep_kernel(const float* __restrict__ Wr) {
    int idx = blockIdx.x * blockDim.x + threadIdx.x;   // 8192 total
    if (idx >= 128 * 64) return;
    int n = idx >> 6;
    int k0 = (idx & 63) * 8;
    unsigned short hs[8], ls[8];
#pragma unroll
    for (int i = 0; i < 8; i++) {
        float x = Wr[(size_t)(k0 + i) * 128 + n];
        hs[i] = f2bf(x);
        ls[i] = f2bf(x - bf2f(hs[i]));
    }
    uint4 uh = make_uint4((unsigned)hs[0] | ((unsigned)hs[1] << 16),
                          (unsigned)hs[2] | ((unsigned)hs[3] << 16),
                          (unsigned)hs[4] | ((unsigned)hs[5] << 16),
                          (unsigned)hs[6] | ((unsigned)hs[7] << 16));
    uint4 ul = make_uint4((unsigned)ls[0] | ((unsigned)ls[1] << 16),
                          (unsigned)ls[2] | ((unsigned)ls[3] << 16),
                          (unsigned)ls[4] | ((unsigned)ls[5] << 16),
                          (unsigned)ls[6] | ((unsigned)ls[7] << 16));
    *(uint4*)(g_wt_hi + (size_t)n * 512 + k0) = uh;
    *(uint4*)(g_wt_lo + (size_t)n * 512 + k0) = ul;
}

// ---------------- aggregation: warp per dst, atomic-free, 8-way ILP ----------------
__global__ void agg_kernel(const float* __restrict__ dst_feat, int n_dst) {
    int warp = (blockIdx.x * blockDim.x + threadIdx.x) >> 5;
    int lane = threadIdx.x & 31;
    if (warp >= n_dst) return;
    int d = warp;
    int beg = g_off[d], end = g_off[d + 1];
    const float4* __restrict__ hv = (const float4*)g_h;

    float4 sum = make_float4(0.f, 0.f, 0.f, 0.f);
    float4 mx  = make_float4(-3.4e38f, -3.4e38f, -3.4e38f, -3.4e38f);

    int e = beg;
    for (; e + 7 < end; e += 8) {
        int s[8];
#pragma unroll
        for (int j = 0; j < 8; j++) s[j] = g_perm[e + j];
        float4 v[8];
#pragma unroll
        for (int j = 0; j < 8; j++) v[j] = hv[s[j] * 32 + lane];
#pragma unroll
        for (int j = 0; j < 8; j++) {
            sum.x += v[j].x; sum.y += v[j].y; sum.z += v[j].z; sum.w += v[j].w;
            mx.x = fmaxf(mx.x, v[j].x); mx.y = fmaxf(mx.y, v[j].y);
            mx.z = fmaxf(mx.z, v[j].z); mx.w = fmaxf(mx.w, v[j].w);
        }
    }
    for (; e < end; e++) {
        int s0 = g_perm[e];
        float4 v0 = hv[s0 * 32 + lane];
        sum.x += v0.x; sum.y += v0.y; sum.z += v0.z; sum.w += v0.w;
        mx.x = fmaxf(mx.x, v0.x); mx.y = fmaxf(mx.y, v0.y);
        mx.z = fmaxf(mx.z, v0.z); mx.w = fmaxf(mx.w, v0.w);
    }

    int cnt = end - beg;
    if (cnt == 0) mx = make_float4(0.f, 0.f, 0.f, 0.f);
    float inv = 1.0f / (float)(cnt > 0 ? cnt : 1);
    float4 mean = make_float4(sum.x * inv, sum.y * inv, sum.z * inv, sum.w * inv);

    float4* out = (float4*)(g_agg + (size_t)d * 4 * H);
    const float4* __restrict__ dfv = (const float4*)dst_feat;
    out[lane]       = sum;
    out[32 + lane]  = mx;
    out[64 + lane]  = mean;
    out[96 + lane]  = dfv[d * 32 + lane];
}

// ---------------- tiling constants (FFMA MLP) ----------------
#define BM 144
#define BN 128
#define BK 16
#define NTHREADS 288
#define HS_PAD 136

// ---------------- fused MLP: h = src + lrelu(src@W1+b1)@W2 + b2 ----------------
__global__ __launch_bounds__(NTHREADS, 1) void mlp_fused_kernel(
    const float* __restrict__ src, const float* __restrict__ W1,
    const float* __restrict__ b1, const float* __restrict__ W2,
    const float* __restrict__ b2, int M)
{
    extern __shared__ float smem[];
    float* Ws = smem;                       // [2][BK][BN]
    float* As = smem + 4096;                // [2][BK][BM]
    float* Hs = smem + 4096 + 4608;         // [BM][HS_PAD]

    int tid = threadIdx.x;
    int block_row = blockIdx.x * BM;
    int tx = tid & 15, ty = tid >> 4;

    int a_row[2], a_col[2], w_k[2], w_n[2];
    bool w_ok[2];
#pragma unroll
    for (int l = 0; l < 2; l++) {
        int flat = tid + l * NTHREADS;
        a_row[l] = flat >> 2;
        a_col[l] = (flat & 3) * 4;
        w_ok[l] = flat < 512;
        int wf = w_ok[l] ? flat : 0;
        w_k[l] = wf >> 5;
        w_n[l] = (wf & 31) * 4;
    }

    float4 a_reg[2], w_reg[2];
    const int ntiles = H / BK;

    {
        auto fetch = [&](int t) {
#pragma unroll
            for (int l = 0; l < 2; l++) {
                int rg = block_row + a_row[l];
                a_reg[l] = (rg < M) ? *(const float4*)(src + (size_t)rg * H + t * BK + a_col[l])
                                    : make_float4(0.f, 0.f, 0.f, 0.f);
                if (w_ok[l])
                    w_reg[l] = *(const float4*)(W1 + (size_t)(t * BK + w_k[l]) * BN + w_n[l]);
            }
        };
        auto stage = [&](int buf) {
#pragma unroll
            for (int l = 0; l < 2; l++) {
                float* Ab = As + buf * (BK * BM);
                Ab[(a_col[l] + 0) * BM + a_row[l]] = a_reg[l].x;
                Ab[(a_col[l] + 1) * BM + a_row[l]] = a_reg[l].y;
                Ab[(a_col[l] + 2) * BM + a_row[l]] = a_reg[l].z;
                Ab[(a_col[l] + 3) * BM + a_row[l]] = a_reg[l].w;
                if (w_ok[l])
                    *(float4*)(Ws + buf * (BK * BN) + w_k[l] * BN + w_n[l]) = w_reg[l];
            }
        };

        float acc[8][8] = {};
        fetch(0); stage(0);
        __syncthreads();
        for (int t = 0; t < ntiles; t++) {
            if (t + 1 < ntiles) fetch(t + 1);
            const float* Ab = As + (t & 1) * (BK * BM);
            const float* Wb = Ws + (t & 1) * (BK * BN);
#pragma unroll
            for (int k = 0; k < BK; k++) {
                float4 a0 = *(const float4*)(Ab + k * BM + ty * 8);
                float4 a1 = *(const float4*)(Ab + k * BM + ty * 8 + 4);
                float4 c0 = *(const float4*)(Wb + k * BN + tx * 8);
                float4 c1 = *(const float4*)(Wb + k * BN + tx * 8 + 4);
                float av[8] = {a0.x, a0.y, a0.z, a0.w, a1.x, a1.y, a1.z, a1.w};
                float bv[8] = {c0.x, c0.y, c0.z, c0.w, c1.x, c1.y, c1.z, c1.w};
#pragma unroll
                for (int i = 0; i < 8; i++)
#pragma unroll
                    for (int j = 0; j < 8; j++)
                        acc[i][j] = fmaf(av[i], bv[j], acc[i][j]);
            }
            if (t + 1 < ntiles) stage((t + 1) & 1);
            __syncthreads();
        }

        float bv[8];
#pragma unroll
        for (int j = 0; j < 8; j++) bv[j] = b1[tx * 8 + j];
#pragma unroll
        for (int i = 0; i < 8; i++) {
            float v[8];
#pragma unroll
            for (int j = 0; j < 8; j++) {
                float t = acc[i][j] + bv[j];
                v[j] = t > 0.f ? t : 0.1f * t;
            }
            float* row = Hs + (ty * 8 + i) * HS_PAD + tx * 8;
            *(float4*)(row)     = make_float4(v[0], v[1], v[2], v[3]);
            *(float4*)(row + 4) = make_float4(v[4], v[5], v[6], v[7]);
        }
    }
    __syncthreads();

    {
        auto fetchW = [&](int t) {
#pragma unroll
            for (int l = 0; l < 2; l++)
                if (w_ok[l])
                    w_reg[l] = *(const float4*)(W2 + (size_t)(t * BK + w_k[l]) * BN + w_n[l]);
        };
        auto stageW = [&](int buf) {
#pragma unroll
            for (int l = 0; l < 2; l++)
                if (w_ok[l])
                    *(float4*)(Ws + buf * (BK * BN) + w_k[l] * BN + w_n[l]) = w_reg[l];
        };

        float acc[8][8] = {};
        fetchW(0); stageW(0);
        __syncthreads();
        for (int t = 0; t < ntiles; t++) {
            if (t + 1 < ntiles) fetchW(t + 1);
            const float* Wb = Ws + (t & 1) * (BK * BN);
#pragma unroll
            for (int k = 0; k < BK; k++) {
                int kk = t * BK + k;
                float av[8];
#pragma unroll
                for (int i = 0; i < 8; i++)
                    av[i] = Hs[(ty * 8 + i) * HS_PAD + kk];
                float4 c0 = *(const float4*)(Wb + k * BN + tx * 8);
                float4 c1 = *(const float4*)(Wb + k * BN + tx * 8 + 4);
                float bv[8] = {c0.x, c0.y, c0.z, c0.w, c1.x, c1.y, c1.z, c1.w};
#pragma unroll
                for (int i = 0; i < 8; i++)
#pragma unroll
                    for (int j = 0; j < 8; j++)
                        acc[i][j] = fmaf(av[i], bv[j], acc[i][j]);
            }
            if (t + 1 < ntiles) stageW((t + 1) & 1);
            __syncthreads();
        }

        float bv[8];
#pragma unroll
        for (int j = 0; j < 8; j++) bv[j] = b2[tx * 8 + j];
#pragma unroll
        for (int i = 0; i < 8; i++) {
            int rg = block_row + ty * 8 + i;
            if (rg >= M) continue;
#pragma unroll
            for (int j = 0; j < 8; j++) {
                float v = acc[i][j] + bv[j] + src[(size_t)rg * H + tx * 8 + j];
                g_h[(size_t)rg * H + tx * 8 + j] = v;
            }
        }
    }
}

// ---------------- mma.sync readout GEMM ----------------
// out[m][n] = dst[m][n] + lrelu( sum_k agg[m][k]*Wr[k][n] + br[n] )
// 3xBF16 compensated: Ahi*Bhi + Ahi*Blo + Alo*Bhi, fp32 accum in registers.
// CTA 128x128, 8 warps (2M x 4N), warp tile 64x32, K chunks of 64.

#define G2_NT 256
#define KC 64
#define KCP 72    // padded row stride (halfs): 144B rows, conflict-free frags
#define G2_SMEM (4 * 128 * KCP * 2)   // Ahi, Alo, Bhi, Blo = 73728 B

__device__ __forceinline__ void mma_bf16(float* c, const unsigned int* a,
                                         const unsigned int* b) {
    asm volatile(
        "mma.sync.aligned.m16n8k16.row.col.f32.bf16.bf16.f32 "
        "{%0,%1,%2,%3}, {%4,%5,%6,%7}, {%8,%9}, {%0,%1,%2,%3};\n"
        : "+f"(c[0]), "+f"(c[1]), "+f"(c[2]), "+f"(c[3])
        : "r"(a[0]), "r"(a[1]), "r"(a[2]), "r"(a[3]), "r"(b[0]), "r"(b[1]));
}

__global__ __launch_bounds__(G2_NT, 1) void gemm2_mma_kernel(
    const float* __restrict__ br, const float* __restrict__ dst_feat,
    float* __restrict__ out, int M)
{
    extern __shared__ __align__(16) unsigned short sh[];
    unsigned short* sAhi = sh;                    // [128][KCP]
    unsigned short* sAlo = sAhi + 128 * KCP;
    unsigned short* sBhi = sAlo + 128 * KCP;
    unsigned short* sBlo = sBhi + 128 * KCP;

    int tid = threadIdx.x;
    int wid = tid >> 5, lane = tid & 31;
    int g = lane >> 2, t = lane & 3;
    int warpM = wid & 1, warpN = wid >> 1;        // 2 x 4 warps
    int block_row = blockIdx.x * 128;

    float acc[4][4][4];
#pragma unroll
    for (int mt = 0; mt < 4; mt++)
#pragma unroll
        for (int nt = 0; nt < 4; nt++)
#pragma unroll
            for (int q = 0; q < 4; q++) acc[mt][nt][q] = 0.f;

    // staging roles: A: row = tid>>1, half = (tid&1)*32 halfs
    int ar = tid >> 1;
    int ak = (tid & 1) * 32;

    for (int c = 0; c < 8; c++) {
        // ---- stage A hi/lo (fp32 -> bf16 split on the fly) ----
        {
            int row = block_row + ar;
            float v[32];
            if (row < M) {
                const float4* p = (const float4*)(g_agg + (size_t)row * 512 + c * KC + ak);
#pragma unroll
                for (int i = 0; i < 8; i++) {
                    float4 q = p[i];
                    v[i * 4 + 0] = q.x; v[i * 4 + 1] = q.y;
                    v[i * 4 + 2] = q.z; v[i * 4 + 3] = q.w;
                }
            } else {
#pragma unroll
                for (int i = 0; i < 32; i++) v[i] = 0.f;
            }
            unsigned short hs[32], ls[32];
#pragma unroll
            for (int i = 0; i < 32; i++) {
                hs[i] = f2bf(v[i]);
                ls[i] = f2bf(v[i] - bf2f(hs[i]));
            }
            unsigned short* dh = sAhi + ar * KCP + ak;
            unsigned short* dl = sAlo + ar * KCP + ak;
#pragma unroll
            for (int q = 0; q < 4; q++) {
                uint4 uh = make_uint4(
                    (unsigned)hs[q*8+0] | ((unsigned)hs[q*8+1] << 16),
                    (unsigned)hs[q*8+2] | ((unsigned)hs[q*8+3] << 16),
                    (unsigned)hs[q*8+4] | ((unsigned)hs[q*8+5] << 16),
                    (unsigned)hs[q*8+6] | ((unsigned)hs[q*8+7] << 16));
                uint4 ul = make_uint4(
                    (unsigned)ls[q*8+0] | ((unsigned)ls[q*8+1] << 16),
                    (unsigned)ls[q*8+2] | ((unsigned)ls[q*8+3] << 16),
                    (unsigned)ls[q*8+4] | ((unsigned)ls[q*8+5] << 16),
                    (unsigned)ls[q*8+6] | ((unsigned)ls[q*8+7] << 16));
                *(uint4*)(dh + q * 8) = uh;
                *(uint4*)(dl + q * 8) = ul;
            }
        }
        // ---- stage B hi/lo (pre-split, straight copy) ----
        {
            const uint4* ph = (const uint4*)(g_wt_hi + (size_t)ar * 512 + c * KC + ak);
            const uint4* pl = (const uint4*)(g_wt_lo + (size_t)ar * 512 + c * KC + ak);
            unsigned short* dh = sBhi + ar * KCP + ak;
            unsigned short* dl = sBlo + ar * KCP + ak;
#pragma unroll
            for (int q = 0; q < 4; q++) {
                *(uint4*)(dh + q * 8) = ph[q];
                *(uint4*)(dl + q * 8) = pl[q];
            }
        }
        __syncthreads();

        // ---- 4 k16-steps of MMAs ----
#pragma unroll
        for (int ks = 0; ks < 4; ks++) {
            int k0 = ks * 16;
            unsigned int ahi[4][4], alo[4][4];
#pragma unroll
            for (int mt = 0; mt < 4; mt++) {
                int r0 = warpM * 64 + mt * 16 + g;
                const unsigned short* base = sAhi + (size_t)r0 * KCP + k0 + 2 * t;
                ahi[mt][0] = *(const unsigned int*)(base);
                ahi[mt][1] = *(const unsigned int*)(base + 8 * KCP);
                ahi[mt][2] = *(const unsigned int*)(base + 8);
                ahi[mt][3] = *(const unsigned int*)(base + 8 * KCP + 8);
                const unsigned short* basel = sAlo + (size_t)r0 * KCP + k0 + 2 * t;
                alo[mt][0] = *(const unsigned int*)(basel);
                alo[mt][1] = *(const unsigned int*)(basel + 8 * KCP);
                alo[mt][2] = *(const unsigned int*)(basel + 8);
                alo[mt][3] = *(const unsigned int*)(basel + 8 * KCP + 8);
            }
            unsigned int bhi[4][2], blo[4][2];
#pragma unroll
            for (int nt = 0; nt < 4; nt++) {
                int n0 = warpN * 32 + nt * 8 + g;
                const unsigned short* base = sBhi + (size_t)n0 * KCP + k0 + 2 * t;
                bhi[nt][0] = *(const unsigned int*)(base);
                bhi[nt][1] = *(const unsigned int*)(base + 8);
                const unsigned short* basel = sBlo + (size_t)n0 * KCP + k0 + 2 * t;
                blo[nt][0] = *(const unsigned int*)(basel);
                blo[nt][1] = *(const unsigned int*)(basel + 8);
            }
#pragma unroll
            for (int mt = 0; mt < 4; mt++)
#pragma unroll
                for (int nt = 0; nt < 4; nt++) {
                    mma_bf16(acc[mt][nt], ahi[mt], bhi[nt]);
                    mma_bf16(acc[mt][nt], ahi[mt], blo[nt]);
                    mma_bf16(acc[mt][nt], alo[mt], bhi[nt]);
                }
        }
        __syncthreads();
    }

    // ---- epilogue: out = dst + lrelu(acc + br) ----
#pragma unroll
    for (int nt = 0; nt < 4; nt++) {
        int n0 = warpN * 32 + nt * 8 + t * 2;
        float b0 = br[n0], b1 = br[n0 + 1];
#pragma unroll
        for (int mt = 0; mt < 4; mt++) {
            int r0 = block_row + warpM * 64 + mt * 16 + g;
            if (r0 < M) {
                float2 dd = *(const float2*)(dst_feat + (size_t)r0 * 128 + n0);
                float x0 = acc[mt][nt][0] + b0; x0 = x0 > 0.f ? x0 : 0.1f * x0;
                float x1 = acc[mt][nt][1] + b1; x1 = x1 > 0.f ? x1 : 0.1f * x1;
                float2 o; o.x = x0 + dd.x; o.y = x1 + dd.y;
                *(float2*)(out + (size_t)r0 * 128 + n0) = o;
            }
            int r1 = r0 + 8;
            if (r1 < M) {
                float2 dd = *(const float2*)(dst_feat + (size_t)r1 * 128 + n0);
                float x0 = acc[mt][nt][2] + b0; x0 = x0 > 0.f ? x0 : 0.1f * x0;
                float x1 = acc[mt][nt][3] + b1; x1 = x1 > 0.f ? x1 : 0.1f * x1;
                float2 o; o.x = x0 + dd.x; o.y = x1 + dd.y;
                *(float2*)(out + (size_t)r1 * 128 + n0) = o;
            }
        }
    }
}

// ---------------- launch ----------------
extern "C" void kernel_launch(void* const* d_in, const int* in_sizes, int n_in,
                              void* d_out, int out_size) {
    const float* src_feat = (const float*)d_in[0];
    const float* dst_feat = (const float*)d_in[1];
    const int*   edge_src = (const int*)d_in[2];
    const int*   edge_dst = (const int*)d_in[3];
    const float* W1 = (const float*)d_in[4];
    const float* b1 = (const float*)d_in[5];
    const float* W2 = (const float*)d_in[6];
    const float* b2 = (const float*)d_in[7];
    const float* Wr = (const float*)d_in[8];
    const float* br = (const float*)d_in[9];
    float* out = (float*)d_out;

    int n_src = in_sizes[0] / H;
    int n_dst = in_sizes[1] / H;
    int E     = in_sizes[2];

    int gm_src = (n_src + BM - 1) / BM;        // 139
    int gm_tc  = (n_dst + 127) / 128;          // 157
    int nb = (n_dst + 1023) / 1024;

    size_t mlp_smem = (size_t)(4096 + 4608 + BM * HS_PAD) * 4;

    static cudaStream_t side = nullptr, side2 = nullptr;
    static cudaEvent_t ev_fork = nullptr, ev_join = nullptr, ev_join2 = nullptr;
    if (!side) {
        cudaStreamCreateWithFlags(&side, cudaStreamNonBlocking);
        cudaStreamCreateWithFlags(&side2, cudaStreamNonBlocking);
        cudaEventCreateWithFlags(&ev_fork, cudaEventDisableTiming);
        cudaEventCreateWithFlags(&ev_join, cudaEventDisableTiming);
        cudaEventCreateWithFlags(&ev_join2, cudaEventDisableTiming);
        cudaFuncSetAttribute(mlp_fused_kernel,
                             cudaFuncAttributeMaxDynamicSharedMemorySize,
                             (int)mlp_smem);
        cudaFuncSetAttribute(gemm2_mma_kernel,
                             cudaFuncAttributeMaxDynamicSharedMemorySize,
                             G2_SMEM);
    }

    cudaEventRecord(ev_fork, 0);
    cudaStreamWaitEvent(side, ev_fork, 0);
    cudaStreamWaitEvent(side2, ev_fork, 0);

    // side: CSR build (gates agg)
    zero_cnt_kernel<<<(n_dst + 255) / 256, 256, 0, side>>>(n_dst);
    count_kernel<<<(E + 1023) / 1024, 256, 0, side>>>(edge_dst, E);
    scan_block_kernel<<<nb, 1024, 0, side>>>(n_dst);
    scan_add_kernel<<<nb, 1024, 0, side>>>(nb, n_dst);
    scatter_kernel<<<(E + 1023) / 1024, 256, 0, side>>>(edge_src, edge_dst, E);
    cudaEventRecord(ev_join, side);

    // side2: W-readout transpose/split (gates gemm2 only)
    wt_prep_kernel<<<32, 256, 0, side2>>>(Wr);
    cudaEventRecord(ev_join2, side2);

    // main: fused src MLP
    mlp_fused_kernel<<<gm_src, NTHREADS, mlp_smem>>>(src_feat, W1, b1, W2, b2, n_src);

    cudaStreamWaitEvent(0, ev_join, 0);
    agg_kernel<<<(n_dst * 32 + 255) / 256, 256>>>(dst_feat, n_dst);

    cudaStreamWaitEvent(0, ev_join2, 0);
    gemm2_mma_kernel<<<gm_tc, G2_NT, G2_SMEM>>>(br, dst_feat, out, n_dst);
}

// round 11
// speedup vs baseline: 2.2216x; 1.2168x over previous
#include <cuda_runtime.h>
#include <cuda_bf16.h>
#include <math.h>

#define H 128
#define MAX_SRC 20000
#define MAX_DST 20000
#define MAX_E   640000

// ---------------- device scratch (no runtime allocation) ----------------
__device__ float g_h[MAX_SRC * H];
// A for readout GEMM, pre-split bf16 hi/lo: [row][512] (sum|max|mean|dst)
__device__ __align__(16) unsigned short g_agg_hi[MAX_DST * 512];
__device__ __align__(16) unsigned short g_agg_lo[MAX_DST * 512];
__device__ int   g_cnt[MAX_DST];
__device__ int   g_off[MAX_DST + 1];
__device__ int   g_cursor[MAX_DST];
__device__ int   g_perm[MAX_E];
__device__ int   g_bsum[32];
// W_readout transposed + bf16 hi/lo split: Wt[n][k], n=0..127, k=0..511
__device__ __align__(16) unsigned short g_wt_hi[128 * 512];
__device__ __align__(16) unsigned short g_wt_lo[128 * 512];

// ---------------- small helpers ----------------
__device__ __forceinline__ unsigned int smem_u32(const void* p) {
    unsigned int a;
    asm("{ .reg .u64 t; cvta.to.shared.u64 t, %1; cvt.u32.u64 %0, t; }"
        : "=r"(a) : "l"(p));
    return a;
}
__device__ __forceinline__ unsigned short f2bf(float x) {
    __nv_bfloat16 h = __float2bfloat16_rn(x);
    return *reinterpret_cast<unsigned short*>(&h);
}
__device__ __forceinline__ float bf2f(unsigned short u) {
    __nv_bfloat16 h = *reinterpret_cast<__nv_bfloat16*>(&u);
    return __bfloat162float(h);
}
// split float4 -> 4 bf16 hi + 4 bf16 lo, store as uint2 each
__device__ __forceinline__ void split_store(unsigned short* oh, unsigned short* ol,
                                            float4 v) {
    unsigned short h0 = f2bf(v.x), h1 = f2bf(v.y), h2 = f2bf(v.z), h3 = f2bf(v.w);
    unsigned short l0 = f2bf(v.x - bf2f(h0));
    unsigned short l1 = f2bf(v.y - bf2f(h1));
    unsigned short l2 = f2bf(v.z - bf2f(h2));
    unsigned short l3 = f2bf(v.w - bf2f(h3));
    uint2 uh = make_uint2((unsigned)h0 | ((unsigned)h1 << 16),
                          (unsigned)h2 | ((unsigned)h3 << 16));
    uint2 ul = make_uint2((unsigned)l0 | ((unsigned)l1 << 16),
                          (unsigned)l2 | ((unsigned)l3 << 16));
    *(uint2*)oh = uh;
    *(uint2*)ol = ul;
}

// ---------------- CSR build ----------------
__global__ void zero_cnt_kernel(int n_dst) {
    int i = blockIdx.x * blockDim.x + threadIdx.x;
    if (i < n_dst) g_cnt[i] = 0;
}

__global__ void count_kernel(const int* __restrict__ edge_dst, int E) {
    int i = (blockIdx.x * blockDim.x + threadIdx.x) * 4;
    if (i + 3 < E) {
        int4 d = *(const int4*)(edge_dst + i);
        atomicAdd(&g_cnt[d.x], 1);
        atomicAdd(&g_cnt[d.y], 1);
        atomicAdd(&g_cnt[d.z], 1);
        atomicAdd(&g_cnt[d.w], 1);
    } else {
        for (int j = 0; j < 4 && i + j < E; j++)
            atomicAdd(&g_cnt[edge_dst[i + j]], 1);
    }
}

__global__ void scan_block_kernel(int n) {
    __shared__ int warp_sums[32];
    int tid = threadIdx.x, lane = tid & 31, wid = tid >> 5;
    int i = blockIdx.x * 1024 + tid;
    int v = (i < n) ? g_cnt[i] : 0;
    int x = v;
#pragma unroll
    for (int d = 1; d < 32; d <<= 1) {
        int t = __shfl_up_sync(0xffffffffu, x, d);
        if (lane >= d) x += t;
    }
    if (lane == 31) warp_sums[wid] = x;
    __syncthreads();
    if (wid == 0) {
        int s = warp_sums[lane];
#pragma unroll
        for (int d = 1; d < 32; d <<= 1) {
            int t = __shfl_up_sync(0xffffffffu, s, d);
            if (lane >= d) s += t;
        }
        warp_sums[lane] = s;
    }
    __syncthreads();
    int warp_pre = (wid == 0) ? 0 : warp_sums[wid - 1];
    int incl = warp_pre + x;
    if (i < n) g_off[i] = incl - v;
    if (tid == 1023) g_bsum[blockIdx.x] = incl;
}

__global__ void scan_add_kernel(int nb, int n) {
    __shared__ int pre[33];
    int tid = threadIdx.x;
    if (tid < 32) {
        int v0 = (tid < nb) ? g_bsum[tid] : 0;
        int v = v0;
#pragma unroll
        for (int d = 1; d < 32; d <<= 1) {
            int t = __shfl_up_sync(0xffffffffu, v, d);
            if (tid >= d) v += t;
        }
        pre[tid] = v - v0;
        if (tid == 31) pre[32] = v;
    }
    __syncthreads();
    int i = blockIdx.x * 1024 + tid;
    if (i < n) {
        int o = g_off[i] + pre[blockIdx.x];
        g_off[i] = o;
        g_cursor[i] = o;
    }
    if (blockIdx.x == 0 && tid == 0) g_off[n] = pre[32];
}

__global__ void scatter_kernel(const int* __restrict__ edge_src,
                               const int* __restrict__ edge_dst, int E) {
    int i = (blockIdx.x * blockDim.x + threadIdx.x) * 4;
    if (i + 3 < E) {
        int4 d = *(const int4*)(edge_dst + i);
        int4 s = *(const int4*)(edge_src + i);
        g_perm[atomicAdd(&g_cursor[d.x], 1)] = s.x;
        g_perm[atomicAdd(&g_cursor[d.y], 1)] = s.y;
        g_perm[atomicAdd(&g_cursor[d.z], 1)] = s.z;
        g_perm[atomicAdd(&g_cursor[d.w], 1)] = s.w;
    } else {
        for (int j = 0; j < 4 && i + j < E; j++) {
            int d = edge_dst[i + j];
            int p = atomicAdd(&g_cursor[d], 1);
            g_perm[p] = edge_src[i + j];
        }
    }
}

// ---------------- W-transpose + bf16 hi/lo prep ----------------
__global__ void wt_prep_kernel(const float* __restrict__ Wr) {
    int idx = blockIdx.x * blockDim.x + threadIdx.x;   // 8192 total
    if (idx >= 128 * 64) return;
    int n = idx >> 6;
    int k0 = (idx & 63) * 8;
    unsigned short hs[8], ls[8];
#pragma unroll
    for (int i = 0; i < 8; i++) {
        float x = Wr[(size_t)(k0 + i) * 128 + n];
        hs[i] = f2bf(x);
        ls[i] = f2bf(x - bf2f(hs[i]));
    }
    uint4 uh = make_uint4((unsigned)hs[0] | ((unsigned)hs[1] << 16),
                          (unsigned)hs[2] | ((unsigned)hs[3] << 16),
                          (unsigned)hs[4] | ((unsigned)hs[5] << 16),
                          (unsigned)hs[6] | ((unsigned)hs[7] << 16));
    uint4 ul = make_uint4((unsigned)ls[0] | ((unsigned)ls[1] << 16),
                          (unsigned)ls[2] | ((unsigned)ls[3] << 16),
                          (unsigned)ls[4] | ((unsigned)ls[5] << 16),
                          (unsigned)ls[6] | ((unsigned)ls[7] << 16));
    *(uint4*)(g_wt_hi + (size_t)n * 512 + k0) = uh;
    *(uint4*)(g_wt_lo + (size_t)n * 512 + k0) = ul;
}

// ---------------- aggregation: warp per dst; emits bf16 hi/lo A rows ----------------
__global__ void agg_kernel(const float* __restrict__ dst_feat, int n_dst) {
    int warp = (blockIdx.x * blockDim.x + threadIdx.x) >> 5;
    int lane = threadIdx.x & 31;
    if (warp >= n_dst) return;
    int d = warp;
    int beg = g_off[d], end = g_off[d + 1];
    const float4* __restrict__ hv = (const float4*)g_h;

    float4 sum = make_float4(0.f, 0.f, 0.f, 0.f);
    float4 mx  = make_float4(-3.4e38f, -3.4e38f, -3.4e38f, -3.4e38f);

    int e = beg;
    for (; e + 7 < end; e += 8) {
        int s[8];
#pragma unroll
        for (int j = 0; j < 8; j++) s[j] = g_perm[e + j];
        float4 v[8];
#pragma unroll
        for (int j = 0; j < 8; j++) v[j] = hv[s[j] * 32 + lane];
#pragma unroll
        for (int j = 0; j < 8; j++) {
            sum.x += v[j].x; sum.y += v[j].y; sum.z += v[j].z; sum.w += v[j].w;
            mx.x = fmaxf(mx.x, v[j].x); mx.y = fmaxf(mx.y, v[j].y);
            mx.z = fmaxf(mx.z, v[j].z); mx.w = fmaxf(mx.w, v[j].w);
        }
    }
    for (; e < end; e++) {
        int s0 = g_perm[e];
        float4 v0 = hv[s0 * 32 + lane];
        sum.x += v0.x; sum.y += v0.y; sum.z += v0.z; sum.w += v0.w;
        mx.x = fmaxf(mx.x, v0.x); mx.y = fmaxf(mx.y, v0.y);
        mx.z = fmaxf(mx.z, v0.z); mx.w = fmaxf(mx.w, v0.w);
    }

    int cnt = end - beg;
    if (cnt == 0) mx = make_float4(0.f, 0.f, 0.f, 0.f);
    float inv = 1.0f / (float)(cnt > 0 ? cnt : 1);
    float4 mean = make_float4(sum.x * inv, sum.y * inv, sum.z * inv, sum.w * inv);
    float4 dv = ((const float4*)dst_feat)[d * 32 + lane];

    unsigned short* oh = g_agg_hi + (size_t)d * 512;
    unsigned short* ol = g_agg_lo + (size_t)d * 512;
    split_store(oh +   0 + lane * 4, ol +   0 + lane * 4, sum);
    split_store(oh + 128 + lane * 4, ol + 128 + lane * 4, mx);
    split_store(oh + 256 + lane * 4, ol + 256 + lane * 4, mean);
    split_store(oh + 384 + lane * 4, ol + 384 + lane * 4, dv);
}

// ---------------- tiling constants (FFMA MLP) ----------------
#define BM 144
#define BN 128
#define BK 16
#define NTHREADS 288
#define HS_PAD 136

// ---------------- fused MLP: h = src + lrelu(src@W1+b1)@W2 + b2 ----------------
__global__ __launch_bounds__(NTHREADS, 1) void mlp_fused_kernel(
    const float* __restrict__ src, const float* __restrict__ W1,
    const float* __restrict__ b1, const float* __restrict__ W2,
    const float* __restrict__ b2, int M)
{
    extern __shared__ float smem[];
    float* Ws = smem;                       // [2][BK][BN]
    float* As = smem + 4096;                // [2][BK][BM]
    float* Hs = smem + 4096 + 4608;         // [BM][HS_PAD]

    int tid = threadIdx.x;
    int block_row = blockIdx.x * BM;
    int tx = tid & 15, ty = tid >> 4;

    int a_row[2], a_col[2], w_k[2], w_n[2];
    bool w_ok[2];
#pragma unroll
    for (int l = 0; l < 2; l++) {
        int flat = tid + l * NTHREADS;
        a_row[l] = flat >> 2;
        a_col[l] = (flat & 3) * 4;
        w_ok[l] = flat < 512;
        int wf = w_ok[l] ? flat : 0;
        w_k[l] = wf >> 5;
        w_n[l] = (wf & 31) * 4;
    }

    float4 a_reg[2], w_reg[2];
    const int ntiles = H / BK;

    {
        auto fetch = [&](int t) {
#pragma unroll
            for (int l = 0; l < 2; l++) {
                int rg = block_row + a_row[l];
                a_reg[l] = (rg < M) ? *(const float4*)(src + (size_t)rg * H + t * BK + a_col[l])
                                    : make_float4(0.f, 0.f, 0.f, 0.f);
                if (w_ok[l])
                    w_reg[l] = *(const float4*)(W1 + (size_t)(t * BK + w_k[l]) * BN + w_n[l]);
            }
        };
        auto stage = [&](int buf) {
#pragma unroll
            for (int l = 0; l < 2; l++) {
                float* Ab = As + buf * (BK * BM);
                Ab[(a_col[l] + 0) * BM + a_row[l]] = a_reg[l].x;
                Ab[(a_col[l] + 1) * BM + a_row[l]] = a_reg[l].y;
                Ab[(a_col[l] + 2) * BM + a_row[l]] = a_reg[l].z;
                Ab[(a_col[l] + 3) * BM + a_row[l]] = a_reg[l].w;
                if (w_ok[l])
                    *(float4*)(Ws + buf * (BK * BN) + w_k[l] * BN + w_n[l]) = w_reg[l];
            }
        };

        float acc[8][8] = {};
        fetch(0); stage(0);
        __syncthreads();
        for (int t = 0; t < ntiles; t++) {
            if (t + 1 < ntiles) fetch(t + 1);
            const float* Ab = As + (t & 1) * (BK * BM);
            const float* Wb = Ws + (t & 1) * (BK * BN);
#pragma unroll
            for (int k = 0; k < BK; k++) {
                float4 a0 = *(const float4*)(Ab + k * BM + ty * 8);
                float4 a1 = *(const float4*)(Ab + k * BM + ty * 8 + 4);
                float4 c0 = *(const float4*)(Wb + k * BN + tx * 8);
                float4 c1 = *(const float4*)(Wb + k * BN + tx * 8 + 4);
                float av[8] = {a0.x, a0.y, a0.z, a0.w, a1.x, a1.y, a1.z, a1.w};
                float bv[8] = {c0.x, c0.y, c0.z, c0.w, c1.x, c1.y, c1.z, c1.w};
#pragma unroll
                for (int i = 0; i < 8; i++)
#pragma unroll
                    for (int j = 0; j < 8; j++)
                        acc[i][j] = fmaf(av[i], bv[j], acc[i][j]);
            }
            if (t + 1 < ntiles) stage((t + 1) & 1);
            __syncthreads();
        }

        float bv[8];
#pragma unroll
        for (int j = 0; j < 8; j++) bv[j] = b1[tx * 8 + j];
#pragma unroll
        for (int i = 0; i < 8; i++) {
            float v[8];
#pragma unroll
            for (int j = 0; j < 8; j++) {
                float t = acc[i][j] + bv[j];
                v[j] = t > 0.f ? t : 0.1f * t;
            }
            float* row = Hs + (ty * 8 + i) * HS_PAD + tx * 8;
            *(float4*)(row)     = make_float4(v[0], v[1], v[2], v[3]);
            *(float4*)(row + 4) = make_float4(v[4], v[5], v[6], v[7]);
        }
    }
    __syncthreads();

    {
        auto fetchW = [&](int t) {
#pragma unroll
            for (int l = 0; l < 2; l++)
                if (w_ok[l])
                    w_reg[l] = *(const float4*)(W2 + (size_t)(t * BK + w_k[l]) * BN + w_n[l]);
        };
        auto stageW = [&](int buf) {
#pragma unroll
            for (int l = 0; l < 2; l++)
                if (w_ok[l])
                    *(float4*)(Ws + buf * (BK * BN) + w_k[l] * BN + w_n[l]) = w_reg[l];
        };

        float acc[8][8] = {};
        fetchW(0); stageW(0);
        __syncthreads();
        for (int t = 0; t < ntiles; t++) {
            if (t + 1 < ntiles) fetchW(t + 1);
            const float* Wb = Ws + (t & 1) * (BK * BN);
#pragma unroll
            for (int k = 0; k < BK; k++) {
                int kk = t * BK + k;
                float av[8];
#pragma unroll
                for (int i = 0; i < 8; i++)
                    av[i] = Hs[(ty * 8 + i) * HS_PAD + kk];
                float4 c0 = *(const float4*)(Wb + k * BN + tx * 8);
                float4 c1 = *(const float4*)(Wb + k * BN + tx * 8 + 4);
                float bv[8] = {c0.x, c0.y, c0.z, c0.w, c1.x, c1.y, c1.z, c1.w};
#pragma unroll
                for (int i = 0; i < 8; i++)
#pragma unroll
                    for (int j = 0; j < 8; j++)
                        acc[i][j] = fmaf(av[i], bv[j], acc[i][j]);
            }
            if (t + 1 < ntiles) stageW((t + 1) & 1);
            __syncthreads();
        }

        float bv[8];
#pragma unroll
        for (int j = 0; j < 8; j++) bv[j] = b2[tx * 8 + j];
#pragma unroll
        for (int i = 0; i < 8; i++) {
            int rg = block_row + ty * 8 + i;
            if (rg >= M) continue;
#pragma unroll
            for (int j = 0; j < 8; j++) {
                float v = acc[i][j] + bv[j] + src[(size_t)rg * H + tx * 8 + j];
                g_h[(size_t)rg * H + tx * 8 + j] = v;
            }
        }
    }
}

// ---------------- mma.sync readout GEMM, cp.async double-buffered ----------------
// out[m][n] = dst[m][n] + lrelu( sum_k agg[m][k]*Wr[k][n] + br[n] )
// A and B both pre-split bf16 hi/lo in global; staging is pure cp.async copy.
// CTA 128x128, 8 warps (2M x 4N), K chunks of 64, 2 smem buffers.

#define G2_NT 256
#define KC 64
#define KCP 72                       // padded row stride (halfs); 144B rows
#define TILE_HALFS (128 * KCP)       // one tile (Ahi|Alo|Bhi|Blo)
#define BUF_HALFS (4 * TILE_HALFS)
#define G2_SMEM (2 * BUF_HALFS * 2)  // bytes = 147456

__device__ __forceinline__ void mma_bf16(float* c, const unsigned int* a,
                                         const unsigned int* b) {
    asm volatile(
        "mma.sync.aligned.m16n8k16.row.col.f32.bf16.bf16.f32 "
        "{%0,%1,%2,%3}, {%4,%5,%6,%7}, {%8,%9}, {%0,%1,%2,%3};\n"
        : "+f"(c[0]), "+f"(c[1]), "+f"(c[2]), "+f"(c[3])
        : "r"(a[0]), "r"(a[1]), "r"(a[2]), "r"(a[3]), "r"(b[0]), "r"(b[1]));
}

__device__ __forceinline__ void cp16(unsigned int daddr, const void* src, int srcsz) {
    asm volatile("cp.async.cg.shared.global [%0], [%1], 16, %2;"
                 :: "r"(daddr), "l"(src), "r"(srcsz));
}

__global__ __launch_bounds__(G2_NT, 1) void gemm2_mma_kernel(
    const float* __restrict__ br, const float* __restrict__ dst_feat,
    float* __restrict__ out, int M)
{
    extern __shared__ __align__(16) unsigned short sh[];
    unsigned int sbase = smem_u32(sh);

    int tid = threadIdx.x;
    int wid = tid >> 5, lane = tid & 31;
    int g = lane >> 2, t = lane & 3;
    int warpM = wid & 1, warpN = wid >> 1;
    int block_row = blockIdx.x * 128;

    float acc[4][4][4];
#pragma unroll
    for (int mt = 0; mt < 4; mt++)
#pragma unroll
        for (int nt = 0; nt < 4; nt++)
#pragma unroll
            for (int q = 0; q < 4; q++) acc[mt][nt][q] = 0.f;

    // stage one chunk into buffer buf via cp.async (4096 x 16B per buffer)
    auto stage = [&](int c, int buf) {
        unsigned int bb = sbase + (unsigned)buf * (BUF_HALFS * 2);
#pragma unroll
        for (int i = 0; i < 16; i++) {
            int flat = i * G2_NT + tid;       // 0..4095
            int tile = flat >> 10;            // 0..3
            int idx = flat & 1023;
            int row = idx >> 3;
            int seg = idx & 7;
            unsigned int daddr = bb + (unsigned)(tile * TILE_HALFS + row * KCP + seg * 8) * 2;
            const unsigned short* src;
            int sz = 16;
            if (tile < 2) {
                int gr = block_row + row;
                const unsigned short* base = (tile == 0) ? g_agg_hi : g_agg_lo;
                src = base + (size_t)min(gr, MAX_DST - 1) * 512 + c * KC + seg * 8;
                if (gr >= M) sz = 0;          // zero-fill OOB rows
            } else {
                const unsigned short* base = (tile == 2) ? g_wt_hi : g_wt_lo;
                src = base + (size_t)row * 512 + c * KC + seg * 8;
            }
            cp16(daddr, src, sz);
        }
        asm volatile("cp.async.commit_group;" ::: "memory");
    };

    stage(0, 0);

    for (int c = 0; c < 8; c++) {
        int buf = c & 1;
        if (c < 7) stage(c + 1, (c + 1) & 1);
        if (c < 7)
            asm volatile("cp.async.wait_group 1;" ::: "memory");
        else
            asm volatile("cp.async.wait_group 0;" ::: "memory");
        __syncthreads();

        const unsigned short* sAhi = sh + (size_t)buf * BUF_HALFS;
        const unsigned short* sAlo = sAhi + TILE_HALFS;
        const unsigned short* sBhi = sAlo + TILE_HALFS;
        const unsigned short* sBlo = sBhi + TILE_HALFS;

#pragma unroll
        for (int ks = 0; ks < 4; ks++) {
            int k0 = ks * 16;
            unsigned int ahi[4][4], alo[4][4];
#pragma unroll
            for (int mt = 0; mt < 4; mt++) {
                int r0 = warpM * 64 + mt * 16 + g;
                const unsigned short* base = sAhi + (size_t)r0 * KCP + k0 + 2 * t;
                ahi[mt][0] = *(const unsigned int*)(base);
                ahi[mt][1] = *(const unsigned int*)(base + 8 * KCP);
                ahi[mt][2] = *(const unsigned int*)(base + 8);
                ahi[mt][3] = *(const unsigned int*)(base + 8 * KCP + 8);
                const unsigned short* basel = sAlo + (size_t)r0 * KCP + k0 + 2 * t;
                alo[mt][0] = *(const unsigned int*)(basel);
                alo[mt][1] = *(const unsigned int*)(basel + 8 * KCP);
                alo[mt][2] = *(const unsigned int*)(basel + 8);
                alo[mt][3] = *(const unsigned int*)(basel + 8 * KCP + 8);
            }
            unsigned int bhi[4][2], blo[4][2];
#pragma unroll
            for (int nt = 0; nt < 4; nt++) {
                int n0 = warpN * 32 + nt * 8 + g;
                const unsigned short* base = sBhi + (size_t)n0 * KCP + k0 + 2 * t;
                bhi[nt][0] = *(const unsigned int*)(base);
                bhi[nt][1] = *(const unsigned int*)(base + 8);
                const unsigned short* basel = sBlo + (size_t)n0 * KCP + k0 + 2 * t;
                blo[nt][0] = *(const unsigned int*)(basel);
                blo[nt][1] = *(const unsigned int*)(basel + 8);
            }
#pragma unroll
            for (int mt = 0; mt < 4; mt++)
#pragma unroll
                for (int nt = 0; nt < 4; nt++) {
                    mma_bf16(acc[mt][nt], ahi[mt], bhi[nt]);
                    mma_bf16(acc[mt][nt], ahi[mt], blo[nt]);
                    mma_bf16(acc[mt][nt], alo[mt], bhi[nt]);
                }
        }
        __syncthreads();
    }

    // ---- epilogue: out = dst + lrelu(acc + br) ----
#pragma unroll
    for (int nt = 0; nt < 4; nt++) {
        int n0 = warpN * 32 + nt * 8 + t * 2;
        float b0 = br[n0], b1 = br[n0 + 1];
#pragma unroll
        for (int mt = 0; mt < 4; mt++) {
            int r0 = block_row + warpM * 64 + mt * 16 + g;
            if (r0 < M) {
                float2 dd = *(const float2*)(dst_feat + (size_t)r0 * 128 + n0);
                float x0 = acc[mt][nt][0] + b0; x0 = x0 > 0.f ? x0 : 0.1f * x0;
                float x1 = acc[mt][nt][1] + b1; x1 = x1 > 0.f ? x1 : 0.1f * x1;
                float2 o; o.x = x0 + dd.x; o.y = x1 + dd.y;
                *(float2*)(out + (size_t)r0 * 128 + n0) = o;
            }
            int r1 = r0 + 8;
            if (r1 < M) {
                float2 dd = *(const float2*)(dst_feat + (size_t)r1 * 128 + n0);
                float x0 = acc[mt][nt][2] + b0; x0 = x0 > 0.f ? x0 : 0.1f * x0;
                float x1 = acc[mt][nt][3] + b1; x1 = x1 > 0.f ? x1 : 0.1f * x1;
                float2 o; o.x = x0 + dd.x; o.y = x1 + dd.y;
                *(float2*)(out + (size_t)r1 * 128 + n0) = o;
            }
        }
    }
}

// ---------------- launch ----------------
extern "C" void kernel_launch(void* const* d_in, const int* in_sizes, int n_in,
                              void* d_out, int out_size) {
    const float* src_feat = (const float*)d_in[0];
    const float* dst_feat = (const float*)d_in[1];
    const int*   edge_src = (const int*)d_in[2];
    const int*   edge_dst = (const int*)d_in[3];
    const float* W1 = (const float*)d_in[4];
    const float* b1 = (const float*)d_in[5];
    const float* W2 = (const float*)d_in[6];
    const float* b2 = (const float*)d_in[7];
    const float* Wr = (const float*)d_in[8];
    const float* br = (const float*)d_in[9];
    float* out = (float*)d_out;

    int n_src = in_sizes[0] / H;
    int n_dst = in_sizes[1] / H;
    int E     = in_sizes[2];

    int gm_src = (n_src + BM - 1) / BM;        // 139
    int gm_tc  = (n_dst + 127) / 128;          // 157
    int nb = (n_dst + 1023) / 1024;

    size_t mlp_smem = (size_t)(4096 + 4608 + BM * HS_PAD) * 4;

    static cudaStream_t side = nullptr, side2 = nullptr;
    static cudaEvent_t ev_fork = nullptr, ev_join = nullptr, ev_join2 = nullptr;
    if (!side) {
        cudaStreamCreateWithFlags(&side, cudaStreamNonBlocking);
        cudaStreamCreateWithFlags(&side2, cudaStreamNonBlocking);
        cudaEventCreateWithFlags(&ev_fork, cudaEventDisableTiming);
        cudaEventCreateWithFlags(&ev_join, cudaEventDisableTiming);
        cudaEventCreateWithFlags(&ev_join2, cudaEventDisableTiming);
        cudaFuncSetAttribute(mlp_fused_kernel,
                             cudaFuncAttributeMaxDynamicSharedMemorySize,
                             (int)mlp_smem);
        cudaFuncSetAttribute(gemm2_mma_kernel,
                             cudaFuncAttributeMaxDynamicSharedMemorySize,
                             G2_SMEM);
    }

    cudaEventRecord(ev_fork, 0);
    cudaStreamWaitEvent(side, ev_fork, 0);
    cudaStreamWaitEvent(side2, ev_fork, 0);

    // side: CSR build (gates agg)
    zero_cnt_kernel<<<(n_dst + 255) / 256, 256, 0, side>>>(n_dst);
    count_kernel<<<(E + 1023) / 1024, 256, 0, side>>>(edge_dst, E);
    scan_block_kernel<<<nb, 1024, 0, side>>>(n_dst);
    scan_add_kernel<<<nb, 1024, 0, side>>>(nb, n_dst);
    scatter_kernel<<<(E + 1023) / 1024, 256, 0, side>>>(edge_src, edge_dst, E);
    cudaEventRecord(ev_join, side);

    // side2: W-readout transpose/split (gates gemm2 only)
    wt_prep_kernel<<<32, 256, 0, side2>>>(Wr);
    cudaEventRecord(ev_join2, side2);

    // main: fused src MLP
    mlp_fused_kernel<<<gm_src, NTHREADS, mlp_smem>>>(src_feat, W1, b1, W2, b2, n_src);

    cudaStreamWaitEvent(0, ev_join, 0);
    agg_kernel<<<(n_dst * 32 + 255) / 256, 256>>>(dst_feat, n_dst);

    cudaStreamWaitEvent(0, ev_join2, 0);
    gemm2_mma_kernel<<<gm_tc, G2_NT, G2_SMEM>>>(br, dst_feat, out, n_dst);
}